// round 13
// baseline (speedup 1.0000x reference)
#include <cuda_runtime.h>
#include <cuda_bf16.h>
#include <math.h>
#include <stdint.h>
#include <string.h>

#define LSEQ 256
#define CZ   128
#define NH   4
#define HD   32
#define MT   (LSEQ*LSEQ)

__device__ __nv_bfloat16 g_qb[MT*CZ];    // q pre-scaled by 1/sqrt(32)
__device__ __nv_bfloat16 g_kb[MT*CZ];
__device__ __nv_bfloat16 g_vb[MT*CZ];
__device__ __nv_bfloat16 g_attb[MT*CZ];
__device__ __nv_bfloat16 g_pairb[MT*CZ]; // pair bf16 (gate GEMM A)
__device__ __nv_bfloat16 g_gateb[MT*CZ]; // sigmoid gate bf16
__device__ float g_bias[NH*MT];          // bias[h][j*256+k]
__device__ __nv_bfloat16 g_WT[5][CZ*CZ]; // Wq,Wk,Wv,Wg,Wo transposed [n][k] bf16

// ---------------------------------------------------------------------------
__device__ __forceinline__ uint32_t cvta_s(const void* p){
    return (uint32_t)__cvta_generic_to_shared(p);
}
__device__ __forceinline__ void ldsm_x4(uint32_t r[4], const void* p){
    uint32_t a = cvta_s(p);
    asm volatile("ldmatrix.sync.aligned.m8n8.x4.shared.b16 {%0,%1,%2,%3},[%4];"
        : "=r"(r[0]),"=r"(r[1]),"=r"(r[2]),"=r"(r[3]) : "r"(a));
}
__device__ __forceinline__ void ldsm_x4t(uint32_t r[4], const void* p){
    uint32_t a = cvta_s(p);
    asm volatile("ldmatrix.sync.aligned.m8n8.x4.trans.shared.b16 {%0,%1,%2,%3},[%4];"
        : "=r"(r[0]),"=r"(r[1]),"=r"(r[2]),"=r"(r[3]) : "r"(a));
}
__device__ __forceinline__ void mma_bf16(float c[4], const uint32_t a[4],
                                         uint32_t b0, uint32_t b1){
    asm volatile("mma.sync.aligned.m16n8k16.row.col.f32.bf16.bf16.f32 "
        "{%0,%1,%2,%3},{%4,%5,%6,%7},{%8,%9},{%0,%1,%2,%3};"
        : "+f"(c[0]),"+f"(c[1]),"+f"(c[2]),"+f"(c[3])
        : "r"(a[0]),"r"(a[1]),"r"(a[2]),"r"(a[3]),"r"(b0),"r"(b1));
}
__device__ __forceinline__ void cp16(const void* smem_dst, const void* gsrc){
    uint32_t d = cvta_s(smem_dst);
    asm volatile("cp.async.ca.shared.global [%0], [%1], 16;" :: "r"(d), "l"(gsrc));
}
__device__ __forceinline__ void cp_commit_wait(){
    asm volatile("cp.async.commit_group;");
    asm volatile("cp.async.wait_group 0;" ::: "memory");
}
__device__ __forceinline__ uint32_t packbf(float x, float y){
    __nv_bfloat162 h = __floats2bfloat162_rn(x, y);
    uint32_t u; memcpy(&u, &h, 4); return u;
}
__device__ __forceinline__ float2 unpackbf(uint32_t u){
    __nv_bfloat162 h; memcpy(&h, &u, 4);
    return make_float2(__low2float(h), __high2float(h));
}
__device__ __forceinline__ float sigf(float x){
    return 1.f/(1.f + __expf(-x));
}

// ---------------------------------------------------------------------------
// Kernel A: coalesced transpose+convert of the 5 weights -> g_WT [n][k] bf16
// grid (5,4,4): one kc slice per block.
// ---------------------------------------------------------------------------
__global__ void __launch_bounds__(256) wconv_kernel(
    const float* __restrict__ Wq, const float* __restrict__ Wk,
    const float* __restrict__ Wv, const float* __restrict__ Wg,
    const float* __restrict__ Wo)
{
    const float* src[5] = {Wq, Wk, Wv, Wg, Wo};
    const float* W = src[blockIdx.x];
    __nv_bfloat16* dst = g_WT[blockIdx.x];
    __shared__ float tile[32][33];
    int n0 = blockIdx.y * 32;
    int k0 = blockIdx.z * 32;
    int tx = threadIdx.x & 31, ty = threadIdx.x >> 5;

    #pragma unroll
    for (int r = 0; r < 4; r++)
        tile[ty + 8*r][tx] = W[(k0 + ty + 8*r)*128 + n0 + tx];
    __syncthreads();
    #pragma unroll
    for (int p = 0; p < 2; p++){
        int idx = threadIdx.x + p*256;
        int nl = idx >> 4, kl = idx & 15;
        *(uint32_t*)(dst + (n0 + nl)*128 + k0 + 2*kl) =
            packbf(tile[2*kl][nl], tile[2*kl+1][nl]);
    }
}

// ---------------------------------------------------------------------------
// Kernel B: fused LN + bias-proj + pairb copy + q/k/v projections (R12-exact).
// smem: zs[128][136] + 2 x wbuf[128][136] = 104448 B, 2 CTA/SM.
// ---------------------------------------------------------------------------
__global__ void __launch_bounds__(256,2) proj_kernel(
    const float* __restrict__ pair, const float* __restrict__ ln_g,
    const float* __restrict__ ln_b, const float* __restrict__ Wbias)
{
    extern __shared__ __nv_bfloat16 sm[];
    __nv_bfloat16* zs = sm;                           // [128][136]
    __nv_bfloat16* bufs[2] = { sm + 17408, sm + 2*17408 };
    int tid  = threadIdx.x;
    int lane = tid & 31;
    int w    = tid >> 5;
    int r0   = blockIdx.x * 128;
    int wm   = w & 3;
    int wn   = (w >> 2) * 64;
    int ec   = 2 * (lane & 3);

    for (int ii = tid; ii < 2048; ii += 256){
        int r = ii >> 4, c = ii & 15;
        cp16(bufs[0] + r*136 + c*8, g_WT[0] + r*128 + c*8);
    }
    asm volatile("cp.async.commit_group;");

    {
        int row = tid >> 1, half = tid & 1;
        const float4* px = (const float4*)(pair + (size_t)(r0+row)*CZ + half*64);
        float4 xv[16];
        float s1 = 0.f, s2 = 0.f;
        #pragma unroll
        for (int i = 0; i < 16; i++){
            xv[i] = px[i];
            s1 += xv[i].x + xv[i].y + xv[i].z + xv[i].w;
            s2 += xv[i].x*xv[i].x + xv[i].y*xv[i].y + xv[i].z*xv[i].z + xv[i].w*xv[i].w;
        }
        s1 += __shfl_xor_sync(0xffffffffu, s1, 1);
        s2 += __shfl_xor_sync(0xffffffffu, s2, 1);
        float mu  = s1 * (1.f/128.f);
        float inv = rsqrtf(s2 * (1.f/128.f) - mu*mu + 1e-5f);
        float p0=0.f, p1=0.f, p2=0.f, p3=0.f;
        const float4* lg4 = (const float4*)ln_g + half*16;
        const float4* lb4 = (const float4*)ln_b + half*16;
        const float4* wb4 = (const float4*)Wbias;
        #pragma unroll
        for (int i = 0; i < 16; i++){
            float4 g = lg4[i], b = lb4[i];
            int c = half*64 + i*4;
            float z0 = (xv[i].x-mu)*inv*g.x + b.x;
            float z1 = (xv[i].y-mu)*inv*g.y + b.y;
            float z2 = (xv[i].z-mu)*inv*g.z + b.z;
            float z3 = (xv[i].w-mu)*inv*g.w + b.w;
            float4 w0 = wb4[c+0]; p0 = fmaf(z0,w0.x,p0); p1 = fmaf(z0,w0.y,p1); p2 = fmaf(z0,w0.z,p2); p3 = fmaf(z0,w0.w,p3);
            float4 w1 = wb4[c+1]; p0 = fmaf(z1,w1.x,p0); p1 = fmaf(z1,w1.y,p1); p2 = fmaf(z1,w1.z,p2); p3 = fmaf(z1,w1.w,p3);
            float4 w2 = wb4[c+2]; p0 = fmaf(z2,w2.x,p0); p1 = fmaf(z2,w2.y,p1); p2 = fmaf(z2,w2.z,p2); p3 = fmaf(z2,w2.w,p3);
            float4 w3 = wb4[c+3]; p0 = fmaf(z3,w3.x,p0); p1 = fmaf(z3,w3.y,p1); p2 = fmaf(z3,w3.z,p2); p3 = fmaf(z3,w3.w,p3);
            *(uint2*)(zs + row*136 + c) = make_uint2(packbf(z0,z1), packbf(z2,z3));
            *(uint2*)(g_pairb + (size_t)(r0+row)*128 + c) =
                make_uint2(packbf(xv[i].x,xv[i].y), packbf(xv[i].z,xv[i].w));
        }
        p0 += __shfl_xor_sync(0xffffffffu, p0, 1);
        p1 += __shfl_xor_sync(0xffffffffu, p1, 1);
        p2 += __shfl_xor_sync(0xffffffffu, p2, 1);
        p3 += __shfl_xor_sync(0xffffffffu, p3, 1);
        if (half == 0){
            int r = r0 + row;
            g_bias[0*MT + r] = p0;
            g_bias[1*MT + r] = p1;
            g_bias[2*MT + r] = p2;
            g_bias[3*MT + r] = p3;
        }
    }
    asm volatile("cp.async.wait_group 0;" ::: "memory");
    __syncthreads();

    __nv_bfloat16* Ol[3] = {g_qb, g_kb, g_vb};
    for (int widx = 0; widx < 3; widx++){
        const __nv_bfloat16* cur = bufs[widx & 1];
        if (widx < 2){
            __nv_bfloat16* nxt = bufs[(widx+1) & 1];
            const __nv_bfloat16* wsrc = g_WT[widx+1];
            for (int ii = tid; ii < 2048; ii += 256){
                int r = ii >> 4, c = ii & 15;
                cp16(nxt + r*136 + c*8, wsrc + r*128 + c*8);
            }
            asm volatile("cp.async.commit_group;");
        }
        float scale = (widx == 0) ? 0.1767766952966369f : 1.0f;
        uint32_t* dst = (uint32_t*)Ol[widx];
        #pragma unroll
        for (int jh = 0; jh < 2; jh++){
            int wn2 = wn + jh*32;
            float acc[2][4][4] = {};
            #pragma unroll
            for (int ksp = 0; ksp < 8; ksp++){
                uint32_t af[2][4];
                #pragma unroll
                for (int t = 0; t < 2; t++)
                    ldsm_x4(af[t], zs + (wm*32 + 16*t + (lane&15))*136
                                       + ksp*16 + 8*(lane>>4));
                uint32_t bf[4][2];
                #pragma unroll
                for (int g = 0; g < 2; g++){
                    uint32_t r4[4];
                    ldsm_x4(r4, cur + (wn2 + 16*g + (lane&7) + 8*((lane>>3)&1))*136
                                    + ksp*16 + 8*(lane>>4));
                    bf[2*g][0]=r4[0];   bf[2*g][1]=r4[2];
                    bf[2*g+1][0]=r4[1]; bf[2*g+1][1]=r4[3];
                }
                #pragma unroll
                for (int t = 0; t < 2; t++)
                    #pragma unroll
                    for (int j = 0; j < 4; j++)
                        mma_bf16(acc[t][j], af[t], bf[j][0], bf[j][1]);
            }
            #pragma unroll
            for (int t = 0; t < 2; t++)
                #pragma unroll
                for (int j = 0; j < 4; j++){
                    int row = r0 + wm*32 + 16*t + (lane>>2);
                    int col = wn2 + 8*j + ec;
                    dst[((size_t)row*128 + col) >> 1]     = packbf(acc[t][j][0]*scale, acc[t][j][1]*scale);
                    dst[((size_t)(row+8)*128 + col) >> 1] = packbf(acc[t][j][2]*scale, acc[t][j][3]*scale);
                }
        }
        if (widx < 2)
            asm volatile("cp.async.wait_group 0;" ::: "memory");
        __syncthreads();
    }
}

// ---------------------------------------------------------------------------
// Kernel C: flash attention (R12-exact). smem 61440 B, 2 CTA/SM.
// ---------------------------------------------------------------------------
__global__ void __launch_bounds__(256,2) attn_kernel()
{
    extern __shared__ __nv_bfloat16 smA[];
    __nv_bfloat16* Qs = smA;              // [256][40]
    __nv_bfloat16* Ks = smA + 256*40;     // [256][40]
    __nv_bfloat16* Vs = smA + 2*256*40;   // [256][40]

    int i = blockIdx.x, h = blockIdx.y;
    int tid = threadIdx.x;
    int lane = tid & 31, w = tid >> 5;
    int wrow = w * 32;

    for (int ii = tid; ii < 1024; ii += 256){
        int r = ii >> 2, c = ii & 3;
        size_t go = (size_t)(i*256 + r)*128 + h*32 + c*8;
        cp16(Qs + r*40 + c*8, g_qb + go);
        cp16(Ks + r*40 + c*8, g_kb + go);
        cp16(Vs + r*40 + c*8, g_vb + go);
    }
    cp_commit_wait();
    __syncthreads();

    uint32_t qa[2][2][4];
    #pragma unroll
    for (int t = 0; t < 2; t++)
        #pragma unroll
        for (int s = 0; s < 2; s++)
            ldsm_x4(qa[t][s], Qs + (wrow + 16*t + (lane&15))*40 + s*16 + 8*(lane>>4));

    float ls[2][2] = {};
    float oacc[2][4][4] = {};
    const float* bias_b = g_bias + (size_t)h*MT;

    for (int nc = 0; nc < 4; nc++){
        float sacc[2][8][4];
        #pragma unroll
        for (int t = 0; t < 2; t++)
            #pragma unroll
            for (int j = 0; j < 8; j++){
                int rl  = wrow + 16*t + (lane>>2);
                int col = nc*64 + 8*j + 2*(lane&3);
                const float* bp = bias_b + (size_t)rl*256 + col;
                float2 b01 = *(const float2*)bp;
                float2 b23 = *(const float2*)(bp + 2048);
                sacc[t][j][0]=b01.x; sacc[t][j][1]=b01.y;
                sacc[t][j][2]=b23.x; sacc[t][j][3]=b23.y;
            }
        #pragma unroll
        for (int s = 0; s < 2; s++){
            uint32_t kb[8][2];
            #pragma unroll
            for (int g = 0; g < 4; g++){
                uint32_t r[4];
                ldsm_x4(r, Ks + (nc*64 + 16*g + (lane&7) + 8*((lane>>3)&1))*40
                              + s*16 + 8*(lane>>4));
                kb[2*g][0]=r[0]; kb[2*g][1]=r[2];
                kb[2*g+1][0]=r[1]; kb[2*g+1][1]=r[3];
            }
            #pragma unroll
            for (int t = 0; t < 2; t++)
                #pragma unroll
                for (int j = 0; j < 8; j++)
                    mma_bf16(sacc[t][j], qa[t][s], kb[j][0], kb[j][1]);
        }

        uint32_t paf[2][4][4];
        #pragma unroll
        for (int t = 0; t < 2; t++){
            float rs0 = 0.f, rs1 = 0.f;
            #pragma unroll
            for (int j = 0; j < 8; j++){
                float p0 = __expf(sacc[t][j][0]);
                float p1 = __expf(sacc[t][j][1]);
                float p2 = __expf(sacc[t][j][2]);
                float p3 = __expf(sacc[t][j][3]);
                rs0 += p0 + p1; rs1 += p2 + p3;
                int s = j >> 1;
                if (!(j & 1)){ paf[t][s][0]=packbf(p0,p1); paf[t][s][1]=packbf(p2,p3); }
                else         { paf[t][s][2]=packbf(p0,p1); paf[t][s][3]=packbf(p2,p3); }
            }
            ls[t][0] += rs0;
            ls[t][1] += rs1;
        }

        #pragma unroll
        for (int s = 0; s < 4; s++){
            uint32_t vb[4][2];
            #pragma unroll
            for (int g = 0; g < 2; g++){
                uint32_t r[4];
                ldsm_x4t(r, Vs + (nc*64 + s*16 + (lane&7) + 8*((lane>>3)&1))*40
                               + 16*g + 8*(lane>>4));
                vb[2*g][0]=r[0];   vb[2*g][1]=r[1];
                vb[2*g+1][0]=r[2]; vb[2*g+1][1]=r[3];
            }
            #pragma unroll
            for (int t = 0; t < 2; t++)
                #pragma unroll
                for (int v = 0; v < 4; v++)
                    mma_bf16(oacc[t][v], paf[t][s], vb[v][0], vb[v][1]);
        }
    }

    uint32_t* dst = (uint32_t*)g_attb;
    #pragma unroll
    for (int t = 0; t < 2; t++){
        float l0 = ls[t][0];
        l0 += __shfl_xor_sync(0xffffffffu, l0, 1);
        l0 += __shfl_xor_sync(0xffffffffu, l0, 2);
        float l1 = ls[t][1];
        l1 += __shfl_xor_sync(0xffffffffu, l1, 1);
        l1 += __shfl_xor_sync(0xffffffffu, l1, 2);
        float inv0 = 1.f/l0, inv1 = 1.f/l1;
        #pragma unroll
        for (int v = 0; v < 4; v++){
            int rowg = i*256 + wrow + 16*t + (lane>>2);
            int col  = h*32 + 8*v + 2*(lane&3);
            dst[((size_t)rowg*128 + col) >> 1]     = packbf(oacc[t][v][0]*inv0, oacc[t][v][1]*inv0);
            dst[((size_t)(rowg+8)*128 + col) >> 1] = packbf(oacc[t][v][2]*inv1, oacc[t][v][3]*inv1);
        }
    }
}

// ---------------------------------------------------------------------------
// Kernel D1: gate = sigmoid(pair @ Wg + bg) -> g_gateb (bf16)
// 16-row warp tiles, acc[4][4] only -> fits 85 regs. 3 CTA/SM, 24 warps.
// smem: ap[128][136] + wg[128][136] = 69632 B.
// ---------------------------------------------------------------------------
__global__ void __launch_bounds__(256,3) gate_kernel(const float* __restrict__ bg)
{
    extern __shared__ __nv_bfloat16 sm[];
    __nv_bfloat16* ap = sm;            // [128][136]
    __nv_bfloat16* wg = sm + 17408;    // [128][136]
    int tid = threadIdx.x;
    int lane = tid & 31, w = tid >> 5;
    int wr = w * 16;
    int ec = 2 * (lane & 3);
    int r0 = blockIdx.x * 128;

    for (int ii = tid; ii < 2048; ii += 256){
        int r = ii >> 4, c = ii & 15;
        cp16(ap + r*136 + c*8, g_pairb + (size_t)(r0+r)*128 + c*8);
        cp16(wg + r*136 + c*8, g_WT[3] + r*128 + c*8);
    }
    cp_commit_wait();
    __syncthreads();

    uint32_t* gdst = (uint32_t*)g_gateb;
    #pragma unroll
    for (int jh = 0; jh < 4; jh++){
        int wn2 = jh*32;
        float acc[4][4] = {};
        #pragma unroll
        for (int ksp = 0; ksp < 8; ksp++){
            uint32_t af[4];
            ldsm_x4(af, ap + (wr + (lane&15))*136 + ksp*16 + 8*(lane>>4));
            uint32_t bf[4][2];
            #pragma unroll
            for (int g = 0; g < 2; g++){
                uint32_t r4[4];
                ldsm_x4(r4, wg + (wn2 + 16*g + (lane&7) + 8*((lane>>3)&1))*136
                               + ksp*16 + 8*(lane>>4));
                bf[2*g][0]=r4[0];   bf[2*g][1]=r4[2];
                bf[2*g+1][0]=r4[1]; bf[2*g+1][1]=r4[3];
            }
            #pragma unroll
            for (int j = 0; j < 4; j++)
                mma_bf16(acc[j], af, bf[j][0], bf[j][1]);
        }
        #pragma unroll
        for (int j = 0; j < 4; j++){
            int col = wn2 + 8*j + ec;
            float2 bg2 = *(const float2*)(bg + col);
            int row = r0 + wr + (lane>>2);
            gdst[((size_t)row*128 + col) >> 1] =
                packbf(sigf(acc[j][0]+bg2.x), sigf(acc[j][1]+bg2.y));
            gdst[((size_t)(row+8)*128 + col) >> 1] =
                packbf(sigf(acc[j][2]+bg2.x), sigf(acc[j][3]+bg2.y));
        }
    }
}

// ---------------------------------------------------------------------------
// Kernel D2: out = pair + gate * (att @ Wo + bo)
// same 16-row tiling, 3 CTA/SM. smem: att[128][136] + wo[128][136] = 69632 B.
// ---------------------------------------------------------------------------
__global__ void __launch_bounds__(256,3) out_kernel(
    const float* __restrict__ pair, const float* __restrict__ bo,
    float* __restrict__ out)
{
    extern __shared__ __nv_bfloat16 sm[];
    __nv_bfloat16* as_ = sm;            // [128][136]
    __nv_bfloat16* wo  = sm + 17408;    // [128][136]
    int tid = threadIdx.x;
    int lane = tid & 31, w = tid >> 5;
    int wr = w * 16;
    int ec = 2 * (lane & 3);
    int r0 = blockIdx.x * 128;

    for (int ii = tid; ii < 2048; ii += 256){
        int r = ii >> 4, c = ii & 15;
        cp16(as_ + r*136 + c*8, g_attb + (size_t)(r0+r)*128 + c*8);
        cp16(wo  + r*136 + c*8, g_WT[4] + r*128 + c*8);
    }
    cp_commit_wait();
    __syncthreads();

    const uint32_t* gsrc = (const uint32_t*)g_gateb;
    #pragma unroll
    for (int jh = 0; jh < 4; jh++){
        int wn2 = jh*32;
        float acc[4][4] = {};
        #pragma unroll
        for (int ksp = 0; ksp < 8; ksp++){
            uint32_t af[4];
            ldsm_x4(af, as_ + (wr + (lane&15))*136 + ksp*16 + 8*(lane>>4));
            uint32_t bf[4][2];
            #pragma unroll
            for (int g = 0; g < 2; g++){
                uint32_t r4[4];
                ldsm_x4(r4, wo + (wn2 + 16*g + (lane&7) + 8*((lane>>3)&1))*136
                               + ksp*16 + 8*(lane>>4));
                bf[2*g][0]=r4[0];   bf[2*g][1]=r4[2];
                bf[2*g+1][0]=r4[1]; bf[2*g+1][1]=r4[3];
            }
            #pragma unroll
            for (int j = 0; j < 4; j++)
                mma_bf16(acc[j], af, bf[j][0], bf[j][1]);
        }
        #pragma unroll
        for (int j = 0; j < 4; j++){
            int col = wn2 + 8*j + ec;
            float2 bo2 = *(const float2*)(bo + col);
            int row = r0 + wr + (lane>>2);
            float2 g01 = unpackbf(gsrc[((size_t)row*128 + col) >> 1]);
            float2 g23 = unpackbf(gsrc[((size_t)(row+8)*128 + col) >> 1]);
            float2 pr0 = *(const float2*)(pair + (size_t)row*128 + col);
            float2 pr1 = *(const float2*)(pair + (size_t)(row+8)*128 + col);
            float2 o0, o1;
            o0.x = pr0.x + g01.x*(acc[j][0] + bo2.x);
            o0.y = pr0.y + g01.y*(acc[j][1] + bo2.y);
            o1.x = pr1.x + g23.x*(acc[j][2] + bo2.x);
            o1.y = pr1.y + g23.y*(acc[j][3] + bo2.y);
            *(float2*)(out + (size_t)row*128 + col) = o0;
            *(float2*)(out + (size_t)(row+8)*128 + col) = o1;
        }
    }
}

// ---------------------------------------------------------------------------
extern "C" void kernel_launch(void* const* d_in, const int* in_sizes, int n_in,
                              void* d_out, int out_size)
{
    const float* pair  = (const float*)d_in[0];
    const float* ln_g  = (const float*)d_in[1];
    const float* ln_b  = (const float*)d_in[2];
    const float* Wq    = (const float*)d_in[3];
    const float* Wk    = (const float*)d_in[4];
    const float* Wv    = (const float*)d_in[5];
    const float* Wbias = (const float*)d_in[6];
    const float* Wo    = (const float*)d_in[7];
    const float* bo    = (const float*)d_in[8];
    const float* Wg    = (const float*)d_in[9];
    const float* bg    = (const float*)d_in[10];
    float* out = (float*)d_out;

    const int smem_proj = 3*17408*2;   // 104448
    const int smem_attn = 3*256*40*2;  // 61440
    const int smem_go   = 2*17408*2;   // 69632
    cudaFuncSetAttribute(proj_kernel, cudaFuncAttributeMaxDynamicSharedMemorySize, smem_proj);
    cudaFuncSetAttribute(attn_kernel, cudaFuncAttributeMaxDynamicSharedMemorySize, smem_attn);
    cudaFuncSetAttribute(gate_kernel, cudaFuncAttributeMaxDynamicSharedMemorySize, smem_go);
    cudaFuncSetAttribute(out_kernel,  cudaFuncAttributeMaxDynamicSharedMemorySize, smem_go);

    dim3 wg(5, 4, 4);
    wconv_kernel<<<wg, 256>>>(Wq, Wk, Wv, Wg, Wo);
    proj_kernel<<<MT/128, 256, smem_proj>>>(pair, ln_g, ln_b, Wbias);
    dim3 ag(LSEQ, NH);
    attn_kernel<<<ag, 256, smem_attn>>>();
    gate_kernel<<<MT/128, 256, smem_go>>>(bg);
    out_kernel<<<MT/128, 256, smem_go>>>(pair, bo, out);
}

// round 14
// speedup vs baseline: 1.0499x; 1.0499x over previous
#include <cuda_runtime.h>
#include <cuda_bf16.h>
#include <math.h>
#include <stdint.h>
#include <string.h>

#define LSEQ 256
#define CZ   128
#define NH   4
#define HD   32
#define MT   (LSEQ*LSEQ)

__device__ __nv_bfloat16 g_qb[MT*CZ];    // q pre-scaled by 1/sqrt(32)
__device__ __nv_bfloat16 g_kb[MT*CZ];
__device__ __nv_bfloat16 g_vb[MT*CZ];
__device__ __nv_bfloat16 g_attb[MT*CZ];
__device__ __nv_bfloat16 g_pairb[MT*CZ]; // pair bf16 (gate GEMM A)
__device__ float g_bias[NH*MT];          // bias[h][j*256+k]
__device__ __nv_bfloat16 g_WT[5][CZ*CZ]; // Wq,Wk,Wv,Wg,Wo transposed [n][k] bf16

// ---------------------------------------------------------------------------
__device__ __forceinline__ uint32_t cvta_s(const void* p){
    return (uint32_t)__cvta_generic_to_shared(p);
}
__device__ __forceinline__ void ldsm_x4(uint32_t r[4], const void* p){
    uint32_t a = cvta_s(p);
    asm volatile("ldmatrix.sync.aligned.m8n8.x4.shared.b16 {%0,%1,%2,%3},[%4];"
        : "=r"(r[0]),"=r"(r[1]),"=r"(r[2]),"=r"(r[3]) : "r"(a));
}
__device__ __forceinline__ void ldsm_x4t(uint32_t r[4], const void* p){
    uint32_t a = cvta_s(p);
    asm volatile("ldmatrix.sync.aligned.m8n8.x4.trans.shared.b16 {%0,%1,%2,%3},[%4];"
        : "=r"(r[0]),"=r"(r[1]),"=r"(r[2]),"=r"(r[3]) : "r"(a));
}
__device__ __forceinline__ void mma_bf16(float c[4], const uint32_t a[4],
                                         uint32_t b0, uint32_t b1){
    asm volatile("mma.sync.aligned.m16n8k16.row.col.f32.bf16.bf16.f32 "
        "{%0,%1,%2,%3},{%4,%5,%6,%7},{%8,%9},{%0,%1,%2,%3};"
        : "+f"(c[0]),"+f"(c[1]),"+f"(c[2]),"+f"(c[3])
        : "r"(a[0]),"r"(a[1]),"r"(a[2]),"r"(a[3]),"r"(b0),"r"(b1));
}
__device__ __forceinline__ void cp16(const void* smem_dst, const void* gsrc){
    uint32_t d = cvta_s(smem_dst);
    asm volatile("cp.async.ca.shared.global [%0], [%1], 16;" :: "r"(d), "l"(gsrc));
}
__device__ __forceinline__ void cp_commit_wait(){
    asm volatile("cp.async.commit_group;");
    asm volatile("cp.async.wait_group 0;" ::: "memory");
}
__device__ __forceinline__ uint32_t packbf(float x, float y){
    __nv_bfloat162 h = __floats2bfloat162_rn(x, y);
    uint32_t u; memcpy(&u, &h, 4); return u;
}
__device__ __forceinline__ float2 unpackbf(uint32_t u){
    __nv_bfloat162 h; memcpy(&h, &u, 4);
    return make_float2(__low2float(h), __high2float(h));
}
__device__ __forceinline__ float sigf(float x){
    return 1.f/(1.f + __expf(-x));
}

// ---------------------------------------------------------------------------
// Kernel A: coalesced transpose+convert of the 5 weights -> g_WT [n][k] bf16
// grid (5,4,4): one kc slice per block.
// ---------------------------------------------------------------------------
__global__ void __launch_bounds__(256) wconv_kernel(
    const float* __restrict__ Wq, const float* __restrict__ Wk,
    const float* __restrict__ Wv, const float* __restrict__ Wg,
    const float* __restrict__ Wo)
{
    const float* src[5] = {Wq, Wk, Wv, Wg, Wo};
    const float* W = src[blockIdx.x];
    __nv_bfloat16* dst = g_WT[blockIdx.x];
    __shared__ float tile[32][33];
    int n0 = blockIdx.y * 32;
    int k0 = blockIdx.z * 32;
    int tx = threadIdx.x & 31, ty = threadIdx.x >> 5;

    #pragma unroll
    for (int r = 0; r < 4; r++)
        tile[ty + 8*r][tx] = W[(k0 + ty + 8*r)*128 + n0 + tx];
    __syncthreads();
    #pragma unroll
    for (int p = 0; p < 2; p++){
        int idx = threadIdx.x + p*256;
        int nl = idx >> 4, kl = idx & 15;
        *(uint32_t*)(dst + (n0 + nl)*128 + k0 + 2*kl) =
            packbf(tile[2*kl][nl], tile[2*kl+1][nl]);
    }
}

// ---------------------------------------------------------------------------
// Kernel B: fused LN + bias-proj + pairb copy + q/k/v projections (R12-exact).
// smem: zs[128][136] + 2 x wbuf[128][136] = 104448 B, 2 CTA/SM.
// ---------------------------------------------------------------------------
__global__ void __launch_bounds__(256,2) proj_kernel(
    const float* __restrict__ pair, const float* __restrict__ ln_g,
    const float* __restrict__ ln_b, const float* __restrict__ Wbias)
{
    extern __shared__ __nv_bfloat16 sm[];
    __nv_bfloat16* zs = sm;                           // [128][136]
    __nv_bfloat16* bufs[2] = { sm + 17408, sm + 2*17408 };
    int tid  = threadIdx.x;
    int lane = tid & 31;
    int w    = tid >> 5;
    int r0   = blockIdx.x * 128;
    int wm   = w & 3;
    int wn   = (w >> 2) * 64;
    int ec   = 2 * (lane & 3);

    for (int ii = tid; ii < 2048; ii += 256){
        int r = ii >> 4, c = ii & 15;
        cp16(bufs[0] + r*136 + c*8, g_WT[0] + r*128 + c*8);
    }
    asm volatile("cp.async.commit_group;");

    {
        int row = tid >> 1, half = tid & 1;
        const float4* px = (const float4*)(pair + (size_t)(r0+row)*CZ + half*64);
        float4 xv[16];
        float s1 = 0.f, s2 = 0.f;
        #pragma unroll
        for (int i = 0; i < 16; i++){
            xv[i] = px[i];
            s1 += xv[i].x + xv[i].y + xv[i].z + xv[i].w;
            s2 += xv[i].x*xv[i].x + xv[i].y*xv[i].y + xv[i].z*xv[i].z + xv[i].w*xv[i].w;
        }
        s1 += __shfl_xor_sync(0xffffffffu, s1, 1);
        s2 += __shfl_xor_sync(0xffffffffu, s2, 1);
        float mu  = s1 * (1.f/128.f);
        float inv = rsqrtf(s2 * (1.f/128.f) - mu*mu + 1e-5f);
        float p0=0.f, p1=0.f, p2=0.f, p3=0.f;
        const float4* lg4 = (const float4*)ln_g + half*16;
        const float4* lb4 = (const float4*)ln_b + half*16;
        const float4* wb4 = (const float4*)Wbias;
        #pragma unroll
        for (int i = 0; i < 16; i++){
            float4 g = lg4[i], b = lb4[i];
            int c = half*64 + i*4;
            float z0 = (xv[i].x-mu)*inv*g.x + b.x;
            float z1 = (xv[i].y-mu)*inv*g.y + b.y;
            float z2 = (xv[i].z-mu)*inv*g.z + b.z;
            float z3 = (xv[i].w-mu)*inv*g.w + b.w;
            float4 w0 = wb4[c+0]; p0 = fmaf(z0,w0.x,p0); p1 = fmaf(z0,w0.y,p1); p2 = fmaf(z0,w0.z,p2); p3 = fmaf(z0,w0.w,p3);
            float4 w1 = wb4[c+1]; p0 = fmaf(z1,w1.x,p0); p1 = fmaf(z1,w1.y,p1); p2 = fmaf(z1,w1.z,p2); p3 = fmaf(z1,w1.w,p3);
            float4 w2 = wb4[c+2]; p0 = fmaf(z2,w2.x,p0); p1 = fmaf(z2,w2.y,p1); p2 = fmaf(z2,w2.z,p2); p3 = fmaf(z2,w2.w,p3);
            float4 w3 = wb4[c+3]; p0 = fmaf(z3,w3.x,p0); p1 = fmaf(z3,w3.y,p1); p2 = fmaf(z3,w3.z,p2); p3 = fmaf(z3,w3.w,p3);
            *(uint2*)(zs + row*136 + c) = make_uint2(packbf(z0,z1), packbf(z2,z3));
            *(uint2*)(g_pairb + (size_t)(r0+row)*128 + c) =
                make_uint2(packbf(xv[i].x,xv[i].y), packbf(xv[i].z,xv[i].w));
        }
        p0 += __shfl_xor_sync(0xffffffffu, p0, 1);
        p1 += __shfl_xor_sync(0xffffffffu, p1, 1);
        p2 += __shfl_xor_sync(0xffffffffu, p2, 1);
        p3 += __shfl_xor_sync(0xffffffffu, p3, 1);
        if (half == 0){
            int r = r0 + row;
            g_bias[0*MT + r] = p0;
            g_bias[1*MT + r] = p1;
            g_bias[2*MT + r] = p2;
            g_bias[3*MT + r] = p3;
        }
    }
    asm volatile("cp.async.wait_group 0;" ::: "memory");
    __syncthreads();

    __nv_bfloat16* Ol[3] = {g_qb, g_kb, g_vb};
    for (int widx = 0; widx < 3; widx++){
        const __nv_bfloat16* cur = bufs[widx & 1];
        if (widx < 2){
            __nv_bfloat16* nxt = bufs[(widx+1) & 1];
            const __nv_bfloat16* wsrc = g_WT[widx+1];
            for (int ii = tid; ii < 2048; ii += 256){
                int r = ii >> 4, c = ii & 15;
                cp16(nxt + r*136 + c*8, wsrc + r*128 + c*8);
            }
            asm volatile("cp.async.commit_group;");
        }
        float scale = (widx == 0) ? 0.1767766952966369f : 1.0f;
        uint32_t* dst = (uint32_t*)Ol[widx];
        #pragma unroll
        for (int jh = 0; jh < 2; jh++){
            int wn2 = wn + jh*32;
            float acc[2][4][4] = {};
            #pragma unroll
            for (int ksp = 0; ksp < 8; ksp++){
                uint32_t af[2][4];
                #pragma unroll
                for (int t = 0; t < 2; t++)
                    ldsm_x4(af[t], zs + (wm*32 + 16*t + (lane&15))*136
                                       + ksp*16 + 8*(lane>>4));
                uint32_t bf[4][2];
                #pragma unroll
                for (int g = 0; g < 2; g++){
                    uint32_t r4[4];
                    ldsm_x4(r4, cur + (wn2 + 16*g + (lane&7) + 8*((lane>>3)&1))*136
                                    + ksp*16 + 8*(lane>>4));
                    bf[2*g][0]=r4[0];   bf[2*g][1]=r4[2];
                    bf[2*g+1][0]=r4[1]; bf[2*g+1][1]=r4[3];
                }
                #pragma unroll
                for (int t = 0; t < 2; t++)
                    #pragma unroll
                    for (int j = 0; j < 4; j++)
                        mma_bf16(acc[t][j], af[t], bf[j][0], bf[j][1]);
            }
            #pragma unroll
            for (int t = 0; t < 2; t++)
                #pragma unroll
                for (int j = 0; j < 4; j++){
                    int row = r0 + wm*32 + 16*t + (lane>>2);
                    int col = wn2 + 8*j + ec;
                    dst[((size_t)row*128 + col) >> 1]     = packbf(acc[t][j][0]*scale, acc[t][j][1]*scale);
                    dst[((size_t)(row+8)*128 + col) >> 1] = packbf(acc[t][j][2]*scale, acc[t][j][3]*scale);
                }
        }
        if (widx < 2)
            asm volatile("cp.async.wait_group 0;" ::: "memory");
        __syncthreads();
    }
}

// ---------------------------------------------------------------------------
// Kernel C: flash attention (R12-exact). smem 61440 B, 2 CTA/SM.
// ---------------------------------------------------------------------------
__global__ void __launch_bounds__(256,2) attn_kernel()
{
    extern __shared__ __nv_bfloat16 smA[];
    __nv_bfloat16* Qs = smA;              // [256][40]
    __nv_bfloat16* Ks = smA + 256*40;     // [256][40]
    __nv_bfloat16* Vs = smA + 2*256*40;   // [256][40]

    int i = blockIdx.x, h = blockIdx.y;
    int tid = threadIdx.x;
    int lane = tid & 31, w = tid >> 5;
    int wrow = w * 32;

    for (int ii = tid; ii < 1024; ii += 256){
        int r = ii >> 2, c = ii & 3;
        size_t go = (size_t)(i*256 + r)*128 + h*32 + c*8;
        cp16(Qs + r*40 + c*8, g_qb + go);
        cp16(Ks + r*40 + c*8, g_kb + go);
        cp16(Vs + r*40 + c*8, g_vb + go);
    }
    cp_commit_wait();
    __syncthreads();

    uint32_t qa[2][2][4];
    #pragma unroll
    for (int t = 0; t < 2; t++)
        #pragma unroll
        for (int s = 0; s < 2; s++)
            ldsm_x4(qa[t][s], Qs + (wrow + 16*t + (lane&15))*40 + s*16 + 8*(lane>>4));

    float ls[2][2] = {};
    float oacc[2][4][4] = {};
    const float* bias_b = g_bias + (size_t)h*MT;

    for (int nc = 0; nc < 4; nc++){
        float sacc[2][8][4];
        #pragma unroll
        for (int t = 0; t < 2; t++)
            #pragma unroll
            for (int j = 0; j < 8; j++){
                int rl  = wrow + 16*t + (lane>>2);
                int col = nc*64 + 8*j + 2*(lane&3);
                const float* bp = bias_b + (size_t)rl*256 + col;
                float2 b01 = *(const float2*)bp;
                float2 b23 = *(const float2*)(bp + 2048);
                sacc[t][j][0]=b01.x; sacc[t][j][1]=b01.y;
                sacc[t][j][2]=b23.x; sacc[t][j][3]=b23.y;
            }
        #pragma unroll
        for (int s = 0; s < 2; s++){
            uint32_t kb[8][2];
            #pragma unroll
            for (int g = 0; g < 4; g++){
                uint32_t r[4];
                ldsm_x4(r, Ks + (nc*64 + 16*g + (lane&7) + 8*((lane>>3)&1))*40
                              + s*16 + 8*(lane>>4));
                kb[2*g][0]=r[0]; kb[2*g][1]=r[2];
                kb[2*g+1][0]=r[1]; kb[2*g+1][1]=r[3];
            }
            #pragma unroll
            for (int t = 0; t < 2; t++)
                #pragma unroll
                for (int j = 0; j < 8; j++)
                    mma_bf16(sacc[t][j], qa[t][s], kb[j][0], kb[j][1]);
        }

        uint32_t paf[2][4][4];
        #pragma unroll
        for (int t = 0; t < 2; t++){
            float rs0 = 0.f, rs1 = 0.f;
            #pragma unroll
            for (int j = 0; j < 8; j++){
                float p0 = __expf(sacc[t][j][0]);
                float p1 = __expf(sacc[t][j][1]);
                float p2 = __expf(sacc[t][j][2]);
                float p3 = __expf(sacc[t][j][3]);
                rs0 += p0 + p1; rs1 += p2 + p3;
                int s = j >> 1;
                if (!(j & 1)){ paf[t][s][0]=packbf(p0,p1); paf[t][s][1]=packbf(p2,p3); }
                else         { paf[t][s][2]=packbf(p0,p1); paf[t][s][3]=packbf(p2,p3); }
            }
            ls[t][0] += rs0;
            ls[t][1] += rs1;
        }

        #pragma unroll
        for (int s = 0; s < 4; s++){
            uint32_t vb[4][2];
            #pragma unroll
            for (int g = 0; g < 2; g++){
                uint32_t r[4];
                ldsm_x4t(r, Vs + (nc*64 + s*16 + (lane&7) + 8*((lane>>3)&1))*40
                               + 16*g + 8*(lane>>4));
                vb[2*g][0]=r[0];   vb[2*g][1]=r[1];
                vb[2*g+1][0]=r[2]; vb[2*g+1][1]=r[3];
            }
            #pragma unroll
            for (int t = 0; t < 2; t++)
                #pragma unroll
                for (int v = 0; v < 4; v++)
                    mma_bf16(oacc[t][v], paf[t][s], vb[v][0], vb[v][1]);
        }
    }

    uint32_t* dst = (uint32_t*)g_attb;
    #pragma unroll
    for (int t = 0; t < 2; t++){
        float l0 = ls[t][0];
        l0 += __shfl_xor_sync(0xffffffffu, l0, 1);
        l0 += __shfl_xor_sync(0xffffffffu, l0, 2);
        float l1 = ls[t][1];
        l1 += __shfl_xor_sync(0xffffffffu, l1, 1);
        l1 += __shfl_xor_sync(0xffffffffu, l1, 2);
        float inv0 = 1.f/l0, inv1 = 1.f/l1;
        #pragma unroll
        for (int v = 0; v < 4; v++){
            int rowg = i*256 + wrow + 16*t + (lane>>2);
            int col  = h*32 + 8*v + 2*(lane&3);
            dst[((size_t)rowg*128 + col) >> 1]     = packbf(oacc[t][v][0]*inv0, oacc[t][v][1]*inv0);
            dst[((size_t)(rowg+8)*128 + col) >> 1] = packbf(oacc[t][v][2]*inv1, oacc[t][v][3]*inv1);
        }
    }
}

// ---------------------------------------------------------------------------
// Kernel D: out = pair + sigmoid(pair@Wg + bg) * (att@Wo + bo)
// Merged, 16-row warp tiles, __launch_bounds__(256,3): 24 warps/SM.
// smem: A[128][136] + W[128][136] = 69632 B -> 3 CTA/SM.
// gate held packed in registers (32 u32) across the restage.
// ---------------------------------------------------------------------------
__global__ void __launch_bounds__(256,3) final_kernel(
    const float* __restrict__ pair, const float* __restrict__ bo,
    const float* __restrict__ bg,   float* __restrict__ out)
{
    extern __shared__ __nv_bfloat16 sm[];
    __nv_bfloat16* as_ = sm;            // [128][136]
    __nv_bfloat16* wb  = sm + 17408;    // [128][136]
    int tid = threadIdx.x;
    int lane = tid & 31, w = tid >> 5;
    int wr = w * 16;
    int ec = 2 * (lane & 3);
    int r0 = blockIdx.x * 128;

    // stage pairb + Wg
    for (int ii = tid; ii < 2048; ii += 256){
        int r = ii >> 4, c = ii & 15;
        cp16(as_ + r*136 + c*8, g_pairb + (size_t)(r0+r)*128 + c*8);
        cp16(wb  + r*136 + c*8, g_WT[3] + r*128 + c*8);
    }
    cp_commit_wait();
    __syncthreads();

    // gate phase: 4 passes of 32 cols, result packed in registers
    uint32_t gate[16][2];
    #pragma unroll
    for (int jh = 0; jh < 4; jh++){
        int wn2 = jh*32;
        float acc[4][4] = {};
        #pragma unroll
        for (int ksp = 0; ksp < 8; ksp++){
            uint32_t af[4];
            ldsm_x4(af, as_ + (wr + (lane&15))*136 + ksp*16 + 8*(lane>>4));
            uint32_t bf[4][2];
            #pragma unroll
            for (int g = 0; g < 2; g++){
                uint32_t r4[4];
                ldsm_x4(r4, wb + (wn2 + 16*g + (lane&7) + 8*((lane>>3)&1))*136
                               + ksp*16 + 8*(lane>>4));
                bf[2*g][0]=r4[0];   bf[2*g][1]=r4[2];
                bf[2*g+1][0]=r4[1]; bf[2*g+1][1]=r4[3];
            }
            #pragma unroll
            for (int j = 0; j < 4; j++)
                mma_bf16(acc[j], af, bf[j][0], bf[j][1]);
        }
        #pragma unroll
        for (int j = 0; j < 4; j++){
            int col = wn2 + 8*j + ec;
            float2 bg2 = *(const float2*)(bg + col);
            gate[jh*4+j][0] = packbf(sigf(acc[j][0]+bg2.x), sigf(acc[j][1]+bg2.y));
            gate[jh*4+j][1] = packbf(sigf(acc[j][2]+bg2.x), sigf(acc[j][3]+bg2.y));
        }
    }
    __syncthreads();

    // restage: att + Wo
    for (int ii = tid; ii < 2048; ii += 256){
        int r = ii >> 4, c = ii & 15;
        cp16(as_ + r*136 + c*8, g_attb + (size_t)(r0+r)*128 + c*8);
        cp16(wb  + r*136 + c*8, g_WT[4] + r*128 + c*8);
    }
    cp_commit_wait();
    __syncthreads();

    // out phase: out = pair + gate * (att @ Wo + bo)
    #pragma unroll
    for (int jh = 0; jh < 4; jh++){
        int wn2 = jh*32;
        float acc[4][4] = {};
        #pragma unroll
        for (int ksp = 0; ksp < 8; ksp++){
            uint32_t af[4];
            ldsm_x4(af, as_ + (wr + (lane&15))*136 + ksp*16 + 8*(lane>>4));
            uint32_t bf[4][2];
            #pragma unroll
            for (int g = 0; g < 2; g++){
                uint32_t r4[4];
                ldsm_x4(r4, wb + (wn2 + 16*g + (lane&7) + 8*((lane>>3)&1))*136
                               + ksp*16 + 8*(lane>>4));
                bf[2*g][0]=r4[0];   bf[2*g][1]=r4[2];
                bf[2*g+1][0]=r4[1]; bf[2*g+1][1]=r4[3];
            }
            #pragma unroll
            for (int j = 0; j < 4; j++)
                mma_bf16(acc[j], af, bf[j][0], bf[j][1]);
        }
        #pragma unroll
        for (int j = 0; j < 4; j++){
            int col = wn2 + 8*j + ec;
            float2 bo2 = *(const float2*)(bo + col);
            int row = r0 + wr + (lane>>2);
            float2 g01 = unpackbf(gate[jh*4+j][0]);
            float2 g23 = unpackbf(gate[jh*4+j][1]);
            float2 pr0 = *(const float2*)(pair + (size_t)row*128 + col);
            float2 pr1 = *(const float2*)(pair + (size_t)(row+8)*128 + col);
            float2 o0, o1;
            o0.x = pr0.x + g01.x*(acc[j][0] + bo2.x);
            o0.y = pr0.y + g01.y*(acc[j][1] + bo2.y);
            o1.x = pr1.x + g23.x*(acc[j][2] + bo2.x);
            o1.y = pr1.y + g23.y*(acc[j][3] + bo2.y);
            *(float2*)(out + (size_t)row*128 + col) = o0;
            *(float2*)(out + (size_t)(row+8)*128 + col) = o1;
        }
    }
}

// ---------------------------------------------------------------------------
extern "C" void kernel_launch(void* const* d_in, const int* in_sizes, int n_in,
                              void* d_out, int out_size)
{
    const float* pair  = (const float*)d_in[0];
    const float* ln_g  = (const float*)d_in[1];
    const float* ln_b  = (const float*)d_in[2];
    const float* Wq    = (const float*)d_in[3];
    const float* Wk    = (const float*)d_in[4];
    const float* Wv    = (const float*)d_in[5];
    const float* Wbias = (const float*)d_in[6];
    const float* Wo    = (const float*)d_in[7];
    const float* bo    = (const float*)d_in[8];
    const float* Wg    = (const float*)d_in[9];
    const float* bg    = (const float*)d_in[10];
    float* out = (float*)d_out;

    const int smem_proj  = 3*17408*2;   // 104448
    const int smem_attn  = 3*256*40*2;  // 61440
    const int smem_final = 2*17408*2;   // 69632
    cudaFuncSetAttribute(proj_kernel,  cudaFuncAttributeMaxDynamicSharedMemorySize, smem_proj);
    cudaFuncSetAttribute(attn_kernel,  cudaFuncAttributeMaxDynamicSharedMemorySize, smem_attn);
    cudaFuncSetAttribute(final_kernel, cudaFuncAttributeMaxDynamicSharedMemorySize, smem_final);

    dim3 wg(5, 4, 4);
    wconv_kernel<<<wg, 256>>>(Wq, Wk, Wv, Wg, Wo);
    proj_kernel<<<MT/128, 256, smem_proj>>>(pair, ln_g, ln_b, Wbias);
    dim3 ag(LSEQ, NH);
    attn_kernel<<<ag, 256, smem_attn>>>();
    final_kernel<<<MT/128, 256, smem_final>>>(pair, bo, bg, out);
}

// round 15
// speedup vs baseline: 1.1720x; 1.1163x over previous
#include <cuda_runtime.h>
#include <cuda_bf16.h>
#include <math.h>
#include <stdint.h>
#include <string.h>

#define LSEQ 256
#define CZ   128
#define NH   4
#define HD   32
#define MT   (LSEQ*LSEQ)

__device__ __nv_bfloat16 g_qb[MT*CZ];    // q pre-scaled by 1/sqrt(32)
__device__ __nv_bfloat16 g_kb[MT*CZ];
__device__ __nv_bfloat16 g_vb[MT*CZ];
__device__ __nv_bfloat16 g_attb[MT*CZ];
__device__ __nv_bfloat16 g_pairb[MT*CZ]; // pair bf16 (gate GEMM A)
__device__ float g_bias[NH*MT];          // bias[h][j*256+k]
__device__ __nv_bfloat16 g_WT[5][CZ*CZ]; // Wq,Wk,Wv,Wg,Wo transposed [n][k] bf16

// ---------------------------------------------------------------------------
__device__ __forceinline__ uint32_t cvta_s(const void* p){
    return (uint32_t)__cvta_generic_to_shared(p);
}
__device__ __forceinline__ void ldsm_x4(uint32_t r[4], const void* p){
    uint32_t a = cvta_s(p);
    asm volatile("ldmatrix.sync.aligned.m8n8.x4.shared.b16 {%0,%1,%2,%3},[%4];"
        : "=r"(r[0]),"=r"(r[1]),"=r"(r[2]),"=r"(r[3]) : "r"(a));
}
__device__ __forceinline__ void ldsm_x4t(uint32_t r[4], const void* p){
    uint32_t a = cvta_s(p);
    asm volatile("ldmatrix.sync.aligned.m8n8.x4.trans.shared.b16 {%0,%1,%2,%3},[%4];"
        : "=r"(r[0]),"=r"(r[1]),"=r"(r[2]),"=r"(r[3]) : "r"(a));
}
__device__ __forceinline__ void mma_bf16(float c[4], const uint32_t a[4],
                                         uint32_t b0, uint32_t b1){
    asm volatile("mma.sync.aligned.m16n8k16.row.col.f32.bf16.bf16.f32 "
        "{%0,%1,%2,%3},{%4,%5,%6,%7},{%8,%9},{%0,%1,%2,%3};"
        : "+f"(c[0]),"+f"(c[1]),"+f"(c[2]),"+f"(c[3])
        : "r"(a[0]),"r"(a[1]),"r"(a[2]),"r"(a[3]),"r"(b0),"r"(b1));
}
__device__ __forceinline__ void cp16(const void* smem_dst, const void* gsrc){
    uint32_t d = cvta_s(smem_dst);
    asm volatile("cp.async.ca.shared.global [%0], [%1], 16;" :: "r"(d), "l"(gsrc));
}
__device__ __forceinline__ void cp_commit_wait(){
    asm volatile("cp.async.commit_group;");
    asm volatile("cp.async.wait_group 0;" ::: "memory");
}
__device__ __forceinline__ uint32_t packbf(float x, float y){
    __nv_bfloat162 h = __floats2bfloat162_rn(x, y);
    uint32_t u; memcpy(&u, &h, 4); return u;
}
__device__ __forceinline__ float2 unpackbf(uint32_t u){
    __nv_bfloat162 h; memcpy(&h, &u, 4);
    return make_float2(__low2float(h), __high2float(h));
}
__device__ __forceinline__ float sigf(float x){
    return 1.f/(1.f + __expf(-x));
}

// ---------------------------------------------------------------------------
// Kernel A: coalesced transpose+convert of the 5 weights -> g_WT [n][k] bf16
// ---------------------------------------------------------------------------
__global__ void __launch_bounds__(256) wconv_kernel(
    const float* __restrict__ Wq, const float* __restrict__ Wk,
    const float* __restrict__ Wv, const float* __restrict__ Wg,
    const float* __restrict__ Wo)
{
    const float* src[5] = {Wq, Wk, Wv, Wg, Wo};
    const float* W = src[blockIdx.x];
    __nv_bfloat16* dst = g_WT[blockIdx.x];
    __shared__ float tile[32][33];
    int n0 = blockIdx.y * 32;
    int k0 = blockIdx.z * 32;
    int tx = threadIdx.x & 31, ty = threadIdx.x >> 5;

    #pragma unroll
    for (int r = 0; r < 4; r++)
        tile[ty + 8*r][tx] = W[(k0 + ty + 8*r)*128 + n0 + tx];
    __syncthreads();
    #pragma unroll
    for (int p = 0; p < 2; p++){
        int idx = threadIdx.x + p*256;
        int nl = idx >> 4, kl = idx & 15;
        *(uint32_t*)(dst + (n0 + nl)*128 + k0 + 2*kl) =
            packbf(tile[2*kl][nl], tile[2*kl+1][nl]);
    }
}

// ---------------------------------------------------------------------------
// Kernel B: fused LN + bias-proj + pairb copy + q/k/v projections (R12-exact).
// smem: zs[128][136] + 2 x wbuf[128][136] = 104448 B, 2 CTA/SM.
// ---------------------------------------------------------------------------
__global__ void __launch_bounds__(256,2) proj_kernel(
    const float* __restrict__ pair, const float* __restrict__ ln_g,
    const float* __restrict__ ln_b, const float* __restrict__ Wbias)
{
    extern __shared__ __nv_bfloat16 sm[];
    __nv_bfloat16* zs = sm;                           // [128][136]
    __nv_bfloat16* bufs[2] = { sm + 17408, sm + 2*17408 };
    int tid  = threadIdx.x;
    int lane = tid & 31;
    int w    = tid >> 5;
    int r0   = blockIdx.x * 128;
    int wm   = w & 3;
    int wn   = (w >> 2) * 64;
    int ec   = 2 * (lane & 3);

    for (int ii = tid; ii < 2048; ii += 256){
        int r = ii >> 4, c = ii & 15;
        cp16(bufs[0] + r*136 + c*8, g_WT[0] + r*128 + c*8);
    }
    asm volatile("cp.async.commit_group;");

    {
        int row = tid >> 1, half = tid & 1;
        const float4* px = (const float4*)(pair + (size_t)(r0+row)*CZ + half*64);
        float4 xv[16];
        float s1 = 0.f, s2 = 0.f;
        #pragma unroll
        for (int i = 0; i < 16; i++){
            xv[i] = px[i];
            s1 += xv[i].x + xv[i].y + xv[i].z + xv[i].w;
            s2 += xv[i].x*xv[i].x + xv[i].y*xv[i].y + xv[i].z*xv[i].z + xv[i].w*xv[i].w;
        }
        s1 += __shfl_xor_sync(0xffffffffu, s1, 1);
        s2 += __shfl_xor_sync(0xffffffffu, s2, 1);
        float mu  = s1 * (1.f/128.f);
        float inv = rsqrtf(s2 * (1.f/128.f) - mu*mu + 1e-5f);
        float p0=0.f, p1=0.f, p2=0.f, p3=0.f;
        const float4* lg4 = (const float4*)ln_g + half*16;
        const float4* lb4 = (const float4*)ln_b + half*16;
        const float4* wb4 = (const float4*)Wbias;
        #pragma unroll
        for (int i = 0; i < 16; i++){
            float4 g = lg4[i], b = lb4[i];
            int c = half*64 + i*4;
            float z0 = (xv[i].x-mu)*inv*g.x + b.x;
            float z1 = (xv[i].y-mu)*inv*g.y + b.y;
            float z2 = (xv[i].z-mu)*inv*g.z + b.z;
            float z3 = (xv[i].w-mu)*inv*g.w + b.w;
            float4 w0 = wb4[c+0]; p0 = fmaf(z0,w0.x,p0); p1 = fmaf(z0,w0.y,p1); p2 = fmaf(z0,w0.z,p2); p3 = fmaf(z0,w0.w,p3);
            float4 w1 = wb4[c+1]; p0 = fmaf(z1,w1.x,p0); p1 = fmaf(z1,w1.y,p1); p2 = fmaf(z1,w1.z,p2); p3 = fmaf(z1,w1.w,p3);
            float4 w2 = wb4[c+2]; p0 = fmaf(z2,w2.x,p0); p1 = fmaf(z2,w2.y,p1); p2 = fmaf(z2,w2.z,p2); p3 = fmaf(z2,w2.w,p3);
            float4 w3 = wb4[c+3]; p0 = fmaf(z3,w3.x,p0); p1 = fmaf(z3,w3.y,p1); p2 = fmaf(z3,w3.z,p2); p3 = fmaf(z3,w3.w,p3);
            *(uint2*)(zs + row*136 + c) = make_uint2(packbf(z0,z1), packbf(z2,z3));
            *(uint2*)(g_pairb + (size_t)(r0+row)*128 + c) =
                make_uint2(packbf(xv[i].x,xv[i].y), packbf(xv[i].z,xv[i].w));
        }
        p0 += __shfl_xor_sync(0xffffffffu, p0, 1);
        p1 += __shfl_xor_sync(0xffffffffu, p1, 1);
        p2 += __shfl_xor_sync(0xffffffffu, p2, 1);
        p3 += __shfl_xor_sync(0xffffffffu, p3, 1);
        if (half == 0){
            int r = r0 + row;
            g_bias[0*MT + r] = p0;
            g_bias[1*MT + r] = p1;
            g_bias[2*MT + r] = p2;
            g_bias[3*MT + r] = p3;
        }
    }
    asm volatile("cp.async.wait_group 0;" ::: "memory");
    __syncthreads();

    __nv_bfloat16* Ol[3] = {g_qb, g_kb, g_vb};
    for (int widx = 0; widx < 3; widx++){
        const __nv_bfloat16* cur = bufs[widx & 1];
        if (widx < 2){
            __nv_bfloat16* nxt = bufs[(widx+1) & 1];
            const __nv_bfloat16* wsrc = g_WT[widx+1];
            for (int ii = tid; ii < 2048; ii += 256){
                int r = ii >> 4, c = ii & 15;
                cp16(nxt + r*136 + c*8, wsrc + r*128 + c*8);
            }
            asm volatile("cp.async.commit_group;");
        }
        float scale = (widx == 0) ? 0.1767766952966369f : 1.0f;
        uint32_t* dst = (uint32_t*)Ol[widx];
        #pragma unroll
        for (int jh = 0; jh < 2; jh++){
            int wn2 = wn + jh*32;
            float acc[2][4][4] = {};
            #pragma unroll
            for (int ksp = 0; ksp < 8; ksp++){
                uint32_t af[2][4];
                #pragma unroll
                for (int t = 0; t < 2; t++)
                    ldsm_x4(af[t], zs + (wm*32 + 16*t + (lane&15))*136
                                       + ksp*16 + 8*(lane>>4));
                uint32_t bf[4][2];
                #pragma unroll
                for (int g = 0; g < 2; g++){
                    uint32_t r4[4];
                    ldsm_x4(r4, cur + (wn2 + 16*g + (lane&7) + 8*((lane>>3)&1))*136
                                    + ksp*16 + 8*(lane>>4));
                    bf[2*g][0]=r4[0];   bf[2*g][1]=r4[2];
                    bf[2*g+1][0]=r4[1]; bf[2*g+1][1]=r4[3];
                }
                #pragma unroll
                for (int t = 0; t < 2; t++)
                    #pragma unroll
                    for (int j = 0; j < 4; j++)
                        mma_bf16(acc[t][j], af[t], bf[j][0], bf[j][1]);
            }
            #pragma unroll
            for (int t = 0; t < 2; t++)
                #pragma unroll
                for (int j = 0; j < 4; j++){
                    int row = r0 + wm*32 + 16*t + (lane>>2);
                    int col = wn2 + 8*j + ec;
                    dst[((size_t)row*128 + col) >> 1]     = packbf(acc[t][j][0]*scale, acc[t][j][1]*scale);
                    dst[((size_t)(row+8)*128 + col) >> 1] = packbf(acc[t][j][2]*scale, acc[t][j][3]*scale);
                }
        }
        if (widx < 2)
            asm volatile("cp.async.wait_group 0;" ::: "memory");
        __syncthreads();
    }
}

// ---------------------------------------------------------------------------
// Kernel C: flash attention (R12 math). grid (NH, LSEQ): h fastest so blocks
// sharing an i run adjacently (L2 line sharing). Triggers dependent launch
// of final_kernel right after staging.
// ---------------------------------------------------------------------------
__global__ void __launch_bounds__(256,2) attn_kernel()
{
    extern __shared__ __nv_bfloat16 smA[];
    __nv_bfloat16* Qs = smA;              // [256][40]
    __nv_bfloat16* Ks = smA + 256*40;     // [256][40]
    __nv_bfloat16* Vs = smA + 2*256*40;   // [256][40]

    int h = blockIdx.x, i = blockIdx.y;
    int tid = threadIdx.x;
    int lane = tid & 31, w = tid >> 5;
    int wrow = w * 32;

    for (int ii = tid; ii < 1024; ii += 256){
        int r = ii >> 2, c = ii & 3;
        size_t go = (size_t)(i*256 + r)*128 + h*32 + c*8;
        cp16(Qs + r*40 + c*8, g_qb + go);
        cp16(Ks + r*40 + c*8, g_kb + go);
        cp16(Vs + r*40 + c*8, g_vb + go);
    }
    asm volatile("griddepcontrol.launch_dependents;" ::: "memory");
    cp_commit_wait();
    __syncthreads();

    uint32_t qa[2][2][4];
    #pragma unroll
    for (int t = 0; t < 2; t++)
        #pragma unroll
        for (int s = 0; s < 2; s++)
            ldsm_x4(qa[t][s], Qs + (wrow + 16*t + (lane&15))*40 + s*16 + 8*(lane>>4));

    float ls[2][2] = {};
    float oacc[2][4][4] = {};
    const float* bias_b = g_bias + (size_t)h*MT;

    for (int nc = 0; nc < 4; nc++){
        float sacc[2][8][4];
        #pragma unroll
        for (int t = 0; t < 2; t++)
            #pragma unroll
            for (int j = 0; j < 8; j++){
                int rl  = wrow + 16*t + (lane>>2);
                int col = nc*64 + 8*j + 2*(lane&3);
                const float* bp = bias_b + (size_t)rl*256 + col;
                float2 b01 = *(const float2*)bp;
                float2 b23 = *(const float2*)(bp + 2048);
                sacc[t][j][0]=b01.x; sacc[t][j][1]=b01.y;
                sacc[t][j][2]=b23.x; sacc[t][j][3]=b23.y;
            }
        #pragma unroll
        for (int s = 0; s < 2; s++){
            uint32_t kb[8][2];
            #pragma unroll
            for (int g = 0; g < 4; g++){
                uint32_t r[4];
                ldsm_x4(r, Ks + (nc*64 + 16*g + (lane&7) + 8*((lane>>3)&1))*40
                              + s*16 + 8*(lane>>4));
                kb[2*g][0]=r[0]; kb[2*g][1]=r[2];
                kb[2*g+1][0]=r[1]; kb[2*g+1][1]=r[3];
            }
            #pragma unroll
            for (int t = 0; t < 2; t++)
                #pragma unroll
                for (int j = 0; j < 8; j++)
                    mma_bf16(sacc[t][j], qa[t][s], kb[j][0], kb[j][1]);
        }

        uint32_t paf[2][4][4];
        #pragma unroll
        for (int t = 0; t < 2; t++){
            float rs0 = 0.f, rs1 = 0.f;
            #pragma unroll
            for (int j = 0; j < 8; j++){
                float p0 = __expf(sacc[t][j][0]);
                float p1 = __expf(sacc[t][j][1]);
                float p2 = __expf(sacc[t][j][2]);
                float p3 = __expf(sacc[t][j][3]);
                rs0 += p0 + p1; rs1 += p2 + p3;
                int s = j >> 1;
                if (!(j & 1)){ paf[t][s][0]=packbf(p0,p1); paf[t][s][1]=packbf(p2,p3); }
                else         { paf[t][s][2]=packbf(p0,p1); paf[t][s][3]=packbf(p2,p3); }
            }
            ls[t][0] += rs0;
            ls[t][1] += rs1;
        }

        #pragma unroll
        for (int s = 0; s < 4; s++){
            uint32_t vb[4][2];
            #pragma unroll
            for (int g = 0; g < 2; g++){
                uint32_t r[4];
                ldsm_x4t(r, Vs + (nc*64 + s*16 + (lane&7) + 8*((lane>>3)&1))*40
                               + 16*g + 8*(lane>>4));
                vb[2*g][0]=r[0];   vb[2*g][1]=r[1];
                vb[2*g+1][0]=r[2]; vb[2*g+1][1]=r[3];
            }
            #pragma unroll
            for (int t = 0; t < 2; t++)
                #pragma unroll
                for (int v = 0; v < 4; v++)
                    mma_bf16(oacc[t][v], paf[t][s], vb[v][0], vb[v][1]);
        }
    }

    uint32_t* dst = (uint32_t*)g_attb;
    #pragma unroll
    for (int t = 0; t < 2; t++){
        float l0 = ls[t][0];
        l0 += __shfl_xor_sync(0xffffffffu, l0, 1);
        l0 += __shfl_xor_sync(0xffffffffu, l0, 2);
        float l1 = ls[t][1];
        l1 += __shfl_xor_sync(0xffffffffu, l1, 1);
        l1 += __shfl_xor_sync(0xffffffffu, l1, 2);
        float inv0 = 1.f/l0, inv1 = 1.f/l1;
        #pragma unroll
        for (int v = 0; v < 4; v++){
            int rowg = i*256 + wrow + 16*t + (lane>>2);
            int col  = h*32 + 8*v + 2*(lane&3);
            dst[((size_t)rowg*128 + col) >> 1]     = packbf(oacc[t][v][0]*inv0, oacc[t][v][1]*inv0);
            dst[((size_t)(rowg+8)*128 + col) >> 1] = packbf(oacc[t][v][2]*inv1, oacc[t][v][3]*inv1);
        }
    }
}

// ---------------------------------------------------------------------------
// Kernel D: out = pair + sigmoid(pair@Wg + bg) * (att@Wo + bo)  (R12 math)
// PDL: gate phase (depends only on proj) runs before griddepcontrol.wait;
// att restage + out phase after. smem 104448 B -> 2 CTA/SM.
// ---------------------------------------------------------------------------
__global__ void __launch_bounds__(256,2) final_kernel(
    const float* __restrict__ pair, const float* __restrict__ bo,
    const float* __restrict__ bg,   float* __restrict__ out)
{
    extern __shared__ __nv_bfloat16 sm[];
    __nv_bfloat16* as_ = sm;            // [128][136]
    __nv_bfloat16* wgS = sm + 17408;    // [128][136]
    __nv_bfloat16* woS = sm + 2*17408;  // [128][136]
    int tid = threadIdx.x;
    int lane = tid & 31, w = tid >> 5;
    int wm = w & 3, wn = (w >> 2) * 64;
    int ec = 2 * (lane & 3);
    int r0 = blockIdx.x * 128;

    // stage pairb + Wg + Wo (all independent of attn)
    for (int ii = tid; ii < 2048; ii += 256){
        int r = ii >> 4, c = ii & 15;
        cp16(as_ + r*136 + c*8, g_pairb + (size_t)(r0+r)*128 + c*8);
        cp16(wgS + r*136 + c*8, g_WT[3] + r*128 + c*8);
        cp16(woS + r*136 + c*8, g_WT[4] + r*128 + c*8);
    }
    cp_commit_wait();
    __syncthreads();

    // gate = sigmoid(pair @ Wg + bg)  -- overlaps attn's drain via PDL
    uint32_t gate[2][8][2];
    #pragma unroll
    for (int jh = 0; jh < 2; jh++){
        int wn2 = wn + jh*32;
        float acc[2][4][4] = {};
        #pragma unroll
        for (int ksp = 0; ksp < 8; ksp++){
            uint32_t af[2][4];
            #pragma unroll
            for (int t = 0; t < 2; t++)
                ldsm_x4(af[t], as_ + (wm*32 + 16*t + (lane&15))*136
                                    + ksp*16 + 8*(lane>>4));
            uint32_t bf[4][2];
            #pragma unroll
            for (int g = 0; g < 2; g++){
                uint32_t r4[4];
                ldsm_x4(r4, wgS + (wn2 + 16*g + (lane&7) + 8*((lane>>3)&1))*136
                                + ksp*16 + 8*(lane>>4));
                bf[2*g][0]=r4[0];   bf[2*g][1]=r4[2];
                bf[2*g+1][0]=r4[1]; bf[2*g+1][1]=r4[3];
            }
            #pragma unroll
            for (int t = 0; t < 2; t++)
                #pragma unroll
                for (int j = 0; j < 4; j++)
                    mma_bf16(acc[t][j], af[t], bf[j][0], bf[j][1]);
        }
        #pragma unroll
        for (int t = 0; t < 2; t++)
            #pragma unroll
            for (int j = 0; j < 4; j++){
                int col = wn2 + 8*j + ec;
                float2 bg2 = *(const float2*)(bg + col);
                gate[t][jh*4+j][0] = packbf(sigf(acc[t][j][0]+bg2.x), sigf(acc[t][j][1]+bg2.y));
                gate[t][jh*4+j][1] = packbf(sigf(acc[t][j][2]+bg2.x), sigf(acc[t][j][3]+bg2.y));
            }
    }
    __syncthreads();

    // wait for attn grid to complete, then restage att tile
    asm volatile("griddepcontrol.wait;" ::: "memory");
    for (int ii = tid; ii < 2048; ii += 256){
        int r = ii >> 4, c = ii & 15;
        cp16(as_ + r*136 + c*8, g_attb + (size_t)(r0+r)*128 + c*8);
    }
    cp_commit_wait();
    __syncthreads();

    // out = pair + gate * (att @ Wo + bo)
    #pragma unroll
    for (int jh = 0; jh < 2; jh++){
        int wn2 = wn + jh*32;
        float acc[2][4][4] = {};
        #pragma unroll
        for (int ksp = 0; ksp < 8; ksp++){
            uint32_t af[2][4];
            #pragma unroll
            for (int t = 0; t < 2; t++)
                ldsm_x4(af[t], as_ + (wm*32 + 16*t + (lane&15))*136
                                    + ksp*16 + 8*(lane>>4));
            uint32_t bf[4][2];
            #pragma unroll
            for (int g = 0; g < 2; g++){
                uint32_t r4[4];
                ldsm_x4(r4, woS + (wn2 + 16*g + (lane&7) + 8*((lane>>3)&1))*136
                                + ksp*16 + 8*(lane>>4));
                bf[2*g][0]=r4[0];   bf[2*g][1]=r4[2];
                bf[2*g+1][0]=r4[1]; bf[2*g+1][1]=r4[3];
            }
            #pragma unroll
            for (int t = 0; t < 2; t++)
                #pragma unroll
                for (int j = 0; j < 4; j++)
                    mma_bf16(acc[t][j], af[t], bf[j][0], bf[j][1]);
        }
        #pragma unroll
        for (int t = 0; t < 2; t++)
            #pragma unroll
            for (int j = 0; j < 4; j++){
                int row = r0 + wm*32 + 16*t + (lane>>2);
                int col = wn2 + 8*j + ec;
                float2 bo2 = *(const float2*)(bo + col);
                float2 g01 = unpackbf(gate[t][jh*4+j][0]);
                float2 g23 = unpackbf(gate[t][jh*4+j][1]);
                float2 pr0 = *(const float2*)(pair + (size_t)row*128 + col);
                float2 pr1 = *(const float2*)(pair + (size_t)(row+8)*128 + col);
                float2 o0, o1;
                o0.x = pr0.x + g01.x*(acc[t][j][0] + bo2.x);
                o0.y = pr0.y + g01.y*(acc[t][j][1] + bo2.y);
                o1.x = pr1.x + g23.x*(acc[t][j][2] + bo2.x);
                o1.y = pr1.y + g23.y*(acc[t][j][3] + bo2.y);
                *(float2*)(out + (size_t)row*128 + col) = o0;
                *(float2*)(out + (size_t)(row+8)*128 + col) = o1;
            }
    }
}

// ---------------------------------------------------------------------------
extern "C" void kernel_launch(void* const* d_in, const int* in_sizes, int n_in,
                              void* d_out, int out_size)
{
    const float* pair  = (const float*)d_in[0];
    const float* ln_g  = (const float*)d_in[1];
    const float* ln_b  = (const float*)d_in[2];
    const float* Wq    = (const float*)d_in[3];
    const float* Wk    = (const float*)d_in[4];
    const float* Wv    = (const float*)d_in[5];
    const float* Wbias = (const float*)d_in[6];
    const float* Wo    = (const float*)d_in[7];
    const float* bo    = (const float*)d_in[8];
    const float* Wg    = (const float*)d_in[9];
    const float* bg    = (const float*)d_in[10];
    float* out = (float*)d_out;

    const int smem_proj  = 3*17408*2;   // 104448
    const int smem_attn  = 3*256*40*2;  // 61440
    const int smem_final = 3*17408*2;   // 104448
    cudaFuncSetAttribute(proj_kernel,  cudaFuncAttributeMaxDynamicSharedMemorySize, smem_proj);
    cudaFuncSetAttribute(attn_kernel,  cudaFuncAttributeMaxDynamicSharedMemorySize, smem_attn);
    cudaFuncSetAttribute(final_kernel, cudaFuncAttributeMaxDynamicSharedMemorySize, smem_final);

    dim3 wg(5, 4, 4);
    wconv_kernel<<<wg, 256>>>(Wq, Wk, Wv, Wg, Wo);
    proj_kernel<<<MT/128, 256, smem_proj>>>(pair, ln_g, ln_b, Wbias);
    dim3 ag(NH, LSEQ);
    attn_kernel<<<ag, 256, smem_attn>>>();

    // final launched with programmatic dependency on attn (PDL)
    cudaLaunchConfig_t cfg = {};
    cfg.gridDim = dim3(MT/128);
    cfg.blockDim = dim3(256);
    cfg.dynamicSmemBytes = smem_final;
    cfg.stream = 0;
    cudaLaunchAttribute attrs[1];
    attrs[0].id = cudaLaunchAttributeProgrammaticStreamSerialization;
    attrs[0].val.programmaticStreamSerializationAllowed = 1;
    cfg.attrs = attrs;
    cfg.numAttrs = 1;
    cudaLaunchKernelEx(&cfg, final_kernel, pair, bo, bg, out);
}

// round 16
// speedup vs baseline: 1.1736x; 1.0014x over previous
#include <cuda_runtime.h>
#include <cuda_bf16.h>
#include <math.h>
#include <stdint.h>
#include <string.h>

#define LSEQ 256
#define CZ   128
#define NH   4
#define HD   32
#define MT   (LSEQ*LSEQ)

__device__ __nv_bfloat16 g_qb[MT*CZ];    // q pre-scaled by 1/sqrt(32)
__device__ __nv_bfloat16 g_kb[MT*CZ];
__device__ __nv_bfloat16 g_vb[MT*CZ];
__device__ __nv_bfloat16 g_attb[MT*CZ];
__device__ __nv_bfloat16 g_pairb[MT*CZ]; // pair bf16 (gate GEMM A)
__device__ float g_bias[NH*MT];          // bias[h][j*256+k]
__device__ __nv_bfloat16 g_WT[5][CZ*CZ]; // Wq,Wk,Wv,Wg,Wo transposed [n][k] bf16

// ---------------------------------------------------------------------------
__device__ __forceinline__ uint32_t cvta_s(const void* p){
    return (uint32_t)__cvta_generic_to_shared(p);
}
__device__ __forceinline__ void ldsm_x4(uint32_t r[4], const void* p){
    uint32_t a = cvta_s(p);
    asm volatile("ldmatrix.sync.aligned.m8n8.x4.shared.b16 {%0,%1,%2,%3},[%4];"
        : "=r"(r[0]),"=r"(r[1]),"=r"(r[2]),"=r"(r[3]) : "r"(a));
}
__device__ __forceinline__ void ldsm_x4t(uint32_t r[4], const void* p){
    uint32_t a = cvta_s(p);
    asm volatile("ldmatrix.sync.aligned.m8n8.x4.trans.shared.b16 {%0,%1,%2,%3},[%4];"
        : "=r"(r[0]),"=r"(r[1]),"=r"(r[2]),"=r"(r[3]) : "r"(a));
}
__device__ __forceinline__ void mma_bf16(float c[4], const uint32_t a[4],
                                         uint32_t b0, uint32_t b1){
    asm volatile("mma.sync.aligned.m16n8k16.row.col.f32.bf16.bf16.f32 "
        "{%0,%1,%2,%3},{%4,%5,%6,%7},{%8,%9},{%0,%1,%2,%3};"
        : "+f"(c[0]),"+f"(c[1]),"+f"(c[2]),"+f"(c[3])
        : "r"(a[0]),"r"(a[1]),"r"(a[2]),"r"(a[3]),"r"(b0),"r"(b1));
}
__device__ __forceinline__ void cp16(const void* smem_dst, const void* gsrc){
    uint32_t d = cvta_s(smem_dst);
    asm volatile("cp.async.ca.shared.global [%0], [%1], 16;" :: "r"(d), "l"(gsrc));
}
__device__ __forceinline__ void cp_commit_wait(){
    asm volatile("cp.async.commit_group;");
    asm volatile("cp.async.wait_group 0;" ::: "memory");
}
__device__ __forceinline__ uint32_t packbf(float x, float y){
    __nv_bfloat162 h = __floats2bfloat162_rn(x, y);
    uint32_t u; memcpy(&u, &h, 4); return u;
}
__device__ __forceinline__ float2 unpackbf(uint32_t u){
    __nv_bfloat162 h; memcpy(&h, &u, 4);
    return make_float2(__low2float(h), __high2float(h));
}
__device__ __forceinline__ float sigf(float x){
    return 1.f/(1.f + __expf(-x));
}

// ---------------------------------------------------------------------------
// Kernel A: coalesced transpose+convert of the 5 weights -> g_WT [n][k] bf16
// grid (5,4,4). Signals dependent (proj) immediately.
// ---------------------------------------------------------------------------
__global__ void __launch_bounds__(256) wconv_kernel(
    const float* __restrict__ Wq, const float* __restrict__ Wk,
    const float* __restrict__ Wv, const float* __restrict__ Wg,
    const float* __restrict__ Wo)
{
    asm volatile("griddepcontrol.launch_dependents;" ::: "memory");
    const float* src[5] = {Wq, Wk, Wv, Wg, Wo};
    const float* W = src[blockIdx.x];
    __nv_bfloat16* dst = g_WT[blockIdx.x];
    __shared__ float tile[32][33];
    int n0 = blockIdx.y * 32;
    int k0 = blockIdx.z * 32;
    int tx = threadIdx.x & 31, ty = threadIdx.x >> 5;

    #pragma unroll
    for (int r = 0; r < 4; r++)
        tile[ty + 8*r][tx] = W[(k0 + ty + 8*r)*128 + n0 + tx];
    __syncthreads();
    #pragma unroll
    for (int p = 0; p < 2; p++){
        int idx = threadIdx.x + p*256;
        int nl = idx >> 4, kl = idx & 15;
        *(uint32_t*)(dst + (n0 + nl)*128 + k0 + 2*kl) =
            packbf(tile[2*kl][nl], tile[2*kl+1][nl]);
    }
}

// ---------------------------------------------------------------------------
// Kernel B: fused LN + bias-proj + pairb copy + q/k/v projections.
// PDL on wconv: LN phase first (independent), then wait, then weights.
// smem: zs[128][136] + 2 x wbuf[128][136] = 104448 B, 2 CTA/SM.
// ---------------------------------------------------------------------------
__global__ void __launch_bounds__(256,2) proj_kernel(
    const float* __restrict__ pair, const float* __restrict__ ln_g,
    const float* __restrict__ ln_b, const float* __restrict__ Wbias)
{
    extern __shared__ __nv_bfloat16 sm[];
    __nv_bfloat16* zs = sm;                           // [128][136]
    __nv_bfloat16* bufs[2] = { sm + 17408, sm + 2*17408 };
    int tid  = threadIdx.x;
    int lane = tid & 31;
    int w    = tid >> 5;
    int r0   = blockIdx.x * 128;
    int wm   = w & 3;
    int wn   = (w >> 2) * 64;
    int ec   = 2 * (lane & 3);

    // ---- LayerNorm + Wbias projection + pairb copy (independent of wconv) --
    {
        int row = tid >> 1, half = tid & 1;
        const float4* px = (const float4*)(pair + (size_t)(r0+row)*CZ + half*64);
        float4 xv[16];
        float s1 = 0.f, s2 = 0.f;
        #pragma unroll
        for (int i = 0; i < 16; i++){
            xv[i] = px[i];
            s1 += xv[i].x + xv[i].y + xv[i].z + xv[i].w;
            s2 += xv[i].x*xv[i].x + xv[i].y*xv[i].y + xv[i].z*xv[i].z + xv[i].w*xv[i].w;
        }
        s1 += __shfl_xor_sync(0xffffffffu, s1, 1);
        s2 += __shfl_xor_sync(0xffffffffu, s2, 1);
        float mu  = s1 * (1.f/128.f);
        float inv = rsqrtf(s2 * (1.f/128.f) - mu*mu + 1e-5f);
        float p0=0.f, p1=0.f, p2=0.f, p3=0.f;
        const float4* lg4 = (const float4*)ln_g + half*16;
        const float4* lb4 = (const float4*)ln_b + half*16;
        const float4* wb4 = (const float4*)Wbias;
        #pragma unroll
        for (int i = 0; i < 16; i++){
            float4 g = lg4[i], b = lb4[i];
            int c = half*64 + i*4;
            float z0 = (xv[i].x-mu)*inv*g.x + b.x;
            float z1 = (xv[i].y-mu)*inv*g.y + b.y;
            float z2 = (xv[i].z-mu)*inv*g.z + b.z;
            float z3 = (xv[i].w-mu)*inv*g.w + b.w;
            float4 w0 = wb4[c+0]; p0 = fmaf(z0,w0.x,p0); p1 = fmaf(z0,w0.y,p1); p2 = fmaf(z0,w0.z,p2); p3 = fmaf(z0,w0.w,p3);
            float4 w1 = wb4[c+1]; p0 = fmaf(z1,w1.x,p0); p1 = fmaf(z1,w1.y,p1); p2 = fmaf(z1,w1.z,p2); p3 = fmaf(z1,w1.w,p3);
            float4 w2 = wb4[c+2]; p0 = fmaf(z2,w2.x,p0); p1 = fmaf(z2,w2.y,p1); p2 = fmaf(z2,w2.z,p2); p3 = fmaf(z2,w2.w,p3);
            float4 w3 = wb4[c+3]; p0 = fmaf(z3,w3.x,p0); p1 = fmaf(z3,w3.y,p1); p2 = fmaf(z3,w3.z,p2); p3 = fmaf(z3,w3.w,p3);
            *(uint2*)(zs + row*136 + c) = make_uint2(packbf(z0,z1), packbf(z2,z3));
            *(uint2*)(g_pairb + (size_t)(r0+row)*128 + c) =
                make_uint2(packbf(xv[i].x,xv[i].y), packbf(xv[i].z,xv[i].w));
        }
        p0 += __shfl_xor_sync(0xffffffffu, p0, 1);
        p1 += __shfl_xor_sync(0xffffffffu, p1, 1);
        p2 += __shfl_xor_sync(0xffffffffu, p2, 1);
        p3 += __shfl_xor_sync(0xffffffffu, p3, 1);
        if (half == 0){
            int r = r0 + row;
            g_bias[0*MT + r] = p0;
            g_bias[1*MT + r] = p1;
            g_bias[2*MT + r] = p2;
            g_bias[3*MT + r] = p3;
        }
    }

    // weights become safe to read only after wconv grid completes
    asm volatile("griddepcontrol.wait;" ::: "memory");
    for (int ii = tid; ii < 2048; ii += 256){
        int r = ii >> 4, c = ii & 15;
        cp16(bufs[0] + r*136 + c*8, g_WT[0] + r*128 + c*8);
    }
    cp_commit_wait();
    __syncthreads();

    __nv_bfloat16* Ol[3] = {g_qb, g_kb, g_vb};
    for (int widx = 0; widx < 3; widx++){
        const __nv_bfloat16* cur = bufs[widx & 1];
        if (widx < 2){
            __nv_bfloat16* nxt = bufs[(widx+1) & 1];
            const __nv_bfloat16* wsrc = g_WT[widx+1];
            for (int ii = tid; ii < 2048; ii += 256){
                int r = ii >> 4, c = ii & 15;
                cp16(nxt + r*136 + c*8, wsrc + r*128 + c*8);
            }
            asm volatile("cp.async.commit_group;");
        }
        float scale = (widx == 0) ? 0.1767766952966369f : 1.0f;
        uint32_t* dst = (uint32_t*)Ol[widx];
        #pragma unroll
        for (int jh = 0; jh < 2; jh++){
            int wn2 = wn + jh*32;
            float acc[2][4][4] = {};
            #pragma unroll
            for (int ksp = 0; ksp < 8; ksp++){
                uint32_t af[2][4];
                #pragma unroll
                for (int t = 0; t < 2; t++)
                    ldsm_x4(af[t], zs + (wm*32 + 16*t + (lane&15))*136
                                       + ksp*16 + 8*(lane>>4));
                uint32_t bf[4][2];
                #pragma unroll
                for (int g = 0; g < 2; g++){
                    uint32_t r4[4];
                    ldsm_x4(r4, cur + (wn2 + 16*g + (lane&7) + 8*((lane>>3)&1))*136
                                    + ksp*16 + 8*(lane>>4));
                    bf[2*g][0]=r4[0];   bf[2*g][1]=r4[2];
                    bf[2*g+1][0]=r4[1]; bf[2*g+1][1]=r4[3];
                }
                #pragma unroll
                for (int t = 0; t < 2; t++)
                    #pragma unroll
                    for (int j = 0; j < 4; j++)
                        mma_bf16(acc[t][j], af[t], bf[j][0], bf[j][1]);
            }
            #pragma unroll
            for (int t = 0; t < 2; t++)
                #pragma unroll
                for (int j = 0; j < 4; j++){
                    int row = r0 + wm*32 + 16*t + (lane>>2);
                    int col = wn2 + 8*j + ec;
                    dst[((size_t)row*128 + col) >> 1]     = packbf(acc[t][j][0]*scale, acc[t][j][1]*scale);
                    dst[((size_t)(row+8)*128 + col) >> 1] = packbf(acc[t][j][2]*scale, acc[t][j][3]*scale);
                }
        }
        if (widx < 2)
            asm volatile("cp.async.wait_group 0;" ::: "memory");
        __syncthreads();
    }
}

// ---------------------------------------------------------------------------
// Kernel C: flash attention (R15-exact). grid (NH, LSEQ), PDL trigger.
// ---------------------------------------------------------------------------
__global__ void __launch_bounds__(256,2) attn_kernel()
{
    extern __shared__ __nv_bfloat16 smA[];
    __nv_bfloat16* Qs = smA;              // [256][40]
    __nv_bfloat16* Ks = smA + 256*40;     // [256][40]
    __nv_bfloat16* Vs = smA + 2*256*40;   // [256][40]

    int h = blockIdx.x, i = blockIdx.y;
    int tid = threadIdx.x;
    int lane = tid & 31, w = tid >> 5;
    int wrow = w * 32;

    for (int ii = tid; ii < 1024; ii += 256){
        int r = ii >> 2, c = ii & 3;
        size_t go = (size_t)(i*256 + r)*128 + h*32 + c*8;
        cp16(Qs + r*40 + c*8, g_qb + go);
        cp16(Ks + r*40 + c*8, g_kb + go);
        cp16(Vs + r*40 + c*8, g_vb + go);
    }
    asm volatile("griddepcontrol.launch_dependents;" ::: "memory");
    cp_commit_wait();
    __syncthreads();

    uint32_t qa[2][2][4];
    #pragma unroll
    for (int t = 0; t < 2; t++)
        #pragma unroll
        for (int s = 0; s < 2; s++)
            ldsm_x4(qa[t][s], Qs + (wrow + 16*t + (lane&15))*40 + s*16 + 8*(lane>>4));

    float ls[2][2] = {};
    float oacc[2][4][4] = {};
    const float* bias_b = g_bias + (size_t)h*MT;

    for (int nc = 0; nc < 4; nc++){
        float sacc[2][8][4];
        #pragma unroll
        for (int t = 0; t < 2; t++)
            #pragma unroll
            for (int j = 0; j < 8; j++){
                int rl  = wrow + 16*t + (lane>>2);
                int col = nc*64 + 8*j + 2*(lane&3);
                const float* bp = bias_b + (size_t)rl*256 + col;
                float2 b01 = *(const float2*)bp;
                float2 b23 = *(const float2*)(bp + 2048);
                sacc[t][j][0]=b01.x; sacc[t][j][1]=b01.y;
                sacc[t][j][2]=b23.x; sacc[t][j][3]=b23.y;
            }
        #pragma unroll
        for (int s = 0; s < 2; s++){
            uint32_t kb[8][2];
            #pragma unroll
            for (int g = 0; g < 4; g++){
                uint32_t r[4];
                ldsm_x4(r, Ks + (nc*64 + 16*g + (lane&7) + 8*((lane>>3)&1))*40
                              + s*16 + 8*(lane>>4));
                kb[2*g][0]=r[0]; kb[2*g][1]=r[2];
                kb[2*g+1][0]=r[1]; kb[2*g+1][1]=r[3];
            }
            #pragma unroll
            for (int t = 0; t < 2; t++)
                #pragma unroll
                for (int j = 0; j < 8; j++)
                    mma_bf16(sacc[t][j], qa[t][s], kb[j][0], kb[j][1]);
        }

        uint32_t paf[2][4][4];
        #pragma unroll
        for (int t = 0; t < 2; t++){
            float rs0 = 0.f, rs1 = 0.f;
            #pragma unroll
            for (int j = 0; j < 8; j++){
                float p0 = __expf(sacc[t][j][0]);
                float p1 = __expf(sacc[t][j][1]);
                float p2 = __expf(sacc[t][j][2]);
                float p3 = __expf(sacc[t][j][3]);
                rs0 += p0 + p1; rs1 += p2 + p3;
                int s = j >> 1;
                if (!(j & 1)){ paf[t][s][0]=packbf(p0,p1); paf[t][s][1]=packbf(p2,p3); }
                else         { paf[t][s][2]=packbf(p0,p1); paf[t][s][3]=packbf(p2,p3); }
            }
            ls[t][0] += rs0;
            ls[t][1] += rs1;
        }

        #pragma unroll
        for (int s = 0; s < 4; s++){
            uint32_t vb[4][2];
            #pragma unroll
            for (int g = 0; g < 2; g++){
                uint32_t r[4];
                ldsm_x4t(r, Vs + (nc*64 + s*16 + (lane&7) + 8*((lane>>3)&1))*40
                               + 16*g + 8*(lane>>4));
                vb[2*g][0]=r[0];   vb[2*g][1]=r[1];
                vb[2*g+1][0]=r[2]; vb[2*g+1][1]=r[3];
            }
            #pragma unroll
            for (int t = 0; t < 2; t++)
                #pragma unroll
                for (int v = 0; v < 4; v++)
                    mma_bf16(oacc[t][v], paf[t][s], vb[v][0], vb[v][1]);
        }
    }

    uint32_t* dst = (uint32_t*)g_attb;
    #pragma unroll
    for (int t = 0; t < 2; t++){
        float l0 = ls[t][0];
        l0 += __shfl_xor_sync(0xffffffffu, l0, 1);
        l0 += __shfl_xor_sync(0xffffffffu, l0, 2);
        float l1 = ls[t][1];
        l1 += __shfl_xor_sync(0xffffffffu, l1, 1);
        l1 += __shfl_xor_sync(0xffffffffu, l1, 2);
        float inv0 = 1.f/l0, inv1 = 1.f/l1;
        #pragma unroll
        for (int v = 0; v < 4; v++){
            int rowg = i*256 + wrow + 16*t + (lane>>2);
            int col  = h*32 + 8*v + 2*(lane&3);
            dst[((size_t)rowg*128 + col) >> 1]     = packbf(oacc[t][v][0]*inv0, oacc[t][v][1]*inv0);
            dst[((size_t)(rowg+8)*128 + col) >> 1] = packbf(oacc[t][v][2]*inv1, oacc[t][v][3]*inv1);
        }
    }
}

// ---------------------------------------------------------------------------
// Kernel D: out = pair + sigmoid(pair@Wg + bg) * (att@Wo + bo)  (R15-exact)
// PDL: gate phase before griddepcontrol.wait; out phase after.
// ---------------------------------------------------------------------------
__global__ void __launch_bounds__(256,2) final_kernel(
    const float* __restrict__ pair, const float* __restrict__ bo,
    const float* __restrict__ bg,   float* __restrict__ out)
{
    extern __shared__ __nv_bfloat16 sm[];
    __nv_bfloat16* as_ = sm;            // [128][136]
    __nv_bfloat16* wgS = sm + 17408;    // [128][136]
    __nv_bfloat16* woS = sm + 2*17408;  // [128][136]
    int tid = threadIdx.x;
    int lane = tid & 31, w = tid >> 5;
    int wm = w & 3, wn = (w >> 2) * 64;
    int ec = 2 * (lane & 3);
    int r0 = blockIdx.x * 128;

    for (int ii = tid; ii < 2048; ii += 256){
        int r = ii >> 4, c = ii & 15;
        cp16(as_ + r*136 + c*8, g_pairb + (size_t)(r0+r)*128 + c*8);
        cp16(wgS + r*136 + c*8, g_WT[3] + r*128 + c*8);
        cp16(woS + r*136 + c*8, g_WT[4] + r*128 + c*8);
    }
    cp_commit_wait();
    __syncthreads();

    uint32_t gate[2][8][2];
    #pragma unroll
    for (int jh = 0; jh < 2; jh++){
        int wn2 = wn + jh*32;
        float acc[2][4][4] = {};
        #pragma unroll
        for (int ksp = 0; ksp < 8; ksp++){
            uint32_t af[2][4];
            #pragma unroll
            for (int t = 0; t < 2; t++)
                ldsm_x4(af[t], as_ + (wm*32 + 16*t + (lane&15))*136
                                    + ksp*16 + 8*(lane>>4));
            uint32_t bf[4][2];
            #pragma unroll
            for (int g = 0; g < 2; g++){
                uint32_t r4[4];
                ldsm_x4(r4, wgS + (wn2 + 16*g + (lane&7) + 8*((lane>>3)&1))*136
                                + ksp*16 + 8*(lane>>4));
                bf[2*g][0]=r4[0];   bf[2*g][1]=r4[2];
                bf[2*g+1][0]=r4[1]; bf[2*g+1][1]=r4[3];
            }
            #pragma unroll
            for (int t = 0; t < 2; t++)
                #pragma unroll
                for (int j = 0; j < 4; j++)
                    mma_bf16(acc[t][j], af[t], bf[j][0], bf[j][1]);
        }
        #pragma unroll
        for (int t = 0; t < 2; t++)
            #pragma unroll
            for (int j = 0; j < 4; j++){
                int col = wn2 + 8*j + ec;
                float2 bg2 = *(const float2*)(bg + col);
                gate[t][jh*4+j][0] = packbf(sigf(acc[t][j][0]+bg2.x), sigf(acc[t][j][1]+bg2.y));
                gate[t][jh*4+j][1] = packbf(sigf(acc[t][j][2]+bg2.x), sigf(acc[t][j][3]+bg2.y));
            }
    }
    __syncthreads();

    asm volatile("griddepcontrol.wait;" ::: "memory");
    for (int ii = tid; ii < 2048; ii += 256){
        int r = ii >> 4, c = ii & 15;
        cp16(as_ + r*136 + c*8, g_attb + (size_t)(r0+r)*128 + c*8);
    }
    cp_commit_wait();
    __syncthreads();

    #pragma unroll
    for (int jh = 0; jh < 2; jh++){
        int wn2 = wn + jh*32;
        float acc[2][4][4] = {};
        #pragma unroll
        for (int ksp = 0; ksp < 8; ksp++){
            uint32_t af[2][4];
            #pragma unroll
            for (int t = 0; t < 2; t++)
                ldsm_x4(af[t], as_ + (wm*32 + 16*t + (lane&15))*136
                                    + ksp*16 + 8*(lane>>4));
            uint32_t bf[4][2];
            #pragma unroll
            for (int g = 0; g < 2; g++){
                uint32_t r4[4];
                ldsm_x4(r4, woS + (wn2 + 16*g + (lane&7) + 8*((lane>>3)&1))*136
                                + ksp*16 + 8*(lane>>4));
                bf[2*g][0]=r4[0];   bf[2*g][1]=r4[2];
                bf[2*g+1][0]=r4[1]; bf[2*g+1][1]=r4[3];
            }
            #pragma unroll
            for (int t = 0; t < 2; t++)
                #pragma unroll
                for (int j = 0; j < 4; j++)
                    mma_bf16(acc[t][j], af[t], bf[j][0], bf[j][1]);
        }
        #pragma unroll
        for (int t = 0; t < 2; t++)
            #pragma unroll
            for (int j = 0; j < 4; j++){
                int row = r0 + wm*32 + 16*t + (lane>>2);
                int col = wn2 + 8*j + ec;
                float2 bo2 = *(const float2*)(bo + col);
                float2 g01 = unpackbf(gate[t][jh*4+j][0]);
                float2 g23 = unpackbf(gate[t][jh*4+j][1]);
                float2 pr0 = *(const float2*)(pair + (size_t)row*128 + col);
                float2 pr1 = *(const float2*)(pair + (size_t)(row+8)*128 + col);
                float2 o0, o1;
                o0.x = pr0.x + g01.x*(acc[t][j][0] + bo2.x);
                o0.y = pr0.y + g01.y*(acc[t][j][1] + bo2.y);
                o1.x = pr1.x + g23.x*(acc[t][j][2] + bo2.x);
                o1.y = pr1.y + g23.y*(acc[t][j][3] + bo2.y);
                *(float2*)(out + (size_t)row*128 + col) = o0;
                *(float2*)(out + (size_t)(row+8)*128 + col) = o1;
            }
    }
}

// ---------------------------------------------------------------------------
extern "C" void kernel_launch(void* const* d_in, const int* in_sizes, int n_in,
                              void* d_out, int out_size)
{
    const float* pair  = (const float*)d_in[0];
    const float* ln_g  = (const float*)d_in[1];
    const float* ln_b  = (const float*)d_in[2];
    const float* Wq    = (const float*)d_in[3];
    const float* Wk    = (const float*)d_in[4];
    const float* Wv    = (const float*)d_in[5];
    const float* Wbias = (const float*)d_in[6];
    const float* Wo    = (const float*)d_in[7];
    const float* bo    = (const float*)d_in[8];
    const float* Wg    = (const float*)d_in[9];
    const float* bg    = (const float*)d_in[10];
    float* out = (float*)d_out;

    const int smem_proj  = 3*17408*2;   // 104448
    const int smem_attn  = 3*256*40*2;  // 61440
    const int smem_final = 3*17408*2;   // 104448
    cudaFuncSetAttribute(proj_kernel,  cudaFuncAttributeMaxDynamicSharedMemorySize, smem_proj);
    cudaFuncSetAttribute(attn_kernel,  cudaFuncAttributeMaxDynamicSharedMemorySize, smem_attn);
    cudaFuncSetAttribute(final_kernel, cudaFuncAttributeMaxDynamicSharedMemorySize, smem_final);

    dim3 wg(5, 4, 4);
    wconv_kernel<<<wg, 256>>>(Wq, Wk, Wv, Wg, Wo);

    // proj launched with programmatic dependency on wconv (PDL)
    {
        cudaLaunchConfig_t cfg = {};
        cfg.gridDim = dim3(MT/128);
        cfg.blockDim = dim3(256);
        cfg.dynamicSmemBytes = smem_proj;
        cfg.stream = 0;
        cudaLaunchAttribute attrs[1];
        attrs[0].id = cudaLaunchAttributeProgrammaticStreamSerialization;
        attrs[0].val.programmaticStreamSerializationAllowed = 1;
        cfg.attrs = attrs;
        cfg.numAttrs = 1;
        cudaLaunchKernelEx(&cfg, proj_kernel, pair, ln_g, ln_b, Wbias);
    }

    dim3 ag(NH, LSEQ);
    attn_kernel<<<ag, 256, smem_attn>>>();

    // final launched with programmatic dependency on attn (PDL)
    {
        cudaLaunchConfig_t cfg = {};
        cfg.gridDim = dim3(MT/128);
        cfg.blockDim = dim3(256);
        cfg.dynamicSmemBytes = smem_final;
        cfg.stream = 0;
        cudaLaunchAttribute attrs[1];
        attrs[0].id = cudaLaunchAttributeProgrammaticStreamSerialization;
        attrs[0].val.programmaticStreamSerializationAllowed = 1;
        cfg.attrs = attrs;
        cfg.numAttrs = 1;
        cudaLaunchKernelEx(&cfg, final_kernel, pair, bo, bg, out);
    }
}

// round 17
// speedup vs baseline: 1.2225x; 1.0417x over previous
#include <cuda_runtime.h>
#include <cuda_bf16.h>
#include <math.h>
#include <stdint.h>
#include <string.h>

#define LSEQ 256
#define CZ   128
#define NH   4
#define HD   32
#define MT   (LSEQ*LSEQ)

__device__ __nv_bfloat16 g_qb[MT*CZ];    // q pre-scaled by 1/sqrt(32)
__device__ __nv_bfloat16 g_kb[MT*CZ];
__device__ __nv_bfloat16 g_vb[MT*CZ];
__device__ __nv_bfloat16 g_attb[MT*CZ];
__device__ __nv_bfloat16 g_pairb[MT*CZ]; // pair bf16 (gate GEMM A)
__device__ __nv_bfloat16 g_biasb[NH*MT]; // bias[h][j*256+k] bf16
__device__ __nv_bfloat16 g_WT[5][CZ*CZ]; // Wq,Wk,Wv,Wg,Wo transposed [n][k] bf16

// ---------------------------------------------------------------------------
__device__ __forceinline__ uint32_t cvta_s(const void* p){
    return (uint32_t)__cvta_generic_to_shared(p);
}
__device__ __forceinline__ void ldsm_x4(uint32_t r[4], const void* p){
    uint32_t a = cvta_s(p);
    asm volatile("ldmatrix.sync.aligned.m8n8.x4.shared.b16 {%0,%1,%2,%3},[%4];"
        : "=r"(r[0]),"=r"(r[1]),"=r"(r[2]),"=r"(r[3]) : "r"(a));
}
__device__ __forceinline__ void ldsm_x4t(uint32_t r[4], const void* p){
    uint32_t a = cvta_s(p);
    asm volatile("ldmatrix.sync.aligned.m8n8.x4.trans.shared.b16 {%0,%1,%2,%3},[%4];"
        : "=r"(r[0]),"=r"(r[1]),"=r"(r[2]),"=r"(r[3]) : "r"(a));
}
__device__ __forceinline__ void mma_bf16(float c[4], const uint32_t a[4],
                                         uint32_t b0, uint32_t b1){
    asm volatile("mma.sync.aligned.m16n8k16.row.col.f32.bf16.bf16.f32 "
        "{%0,%1,%2,%3},{%4,%5,%6,%7},{%8,%9},{%0,%1,%2,%3};"
        : "+f"(c[0]),"+f"(c[1]),"+f"(c[2]),"+f"(c[3])
        : "r"(a[0]),"r"(a[1]),"r"(a[2]),"r"(a[3]),"r"(b0),"r"(b1));
}
__device__ __forceinline__ void cp16(const void* smem_dst, const void* gsrc){
    uint32_t d = cvta_s(smem_dst);
    asm volatile("cp.async.ca.shared.global [%0], [%1], 16;" :: "r"(d), "l"(gsrc));
}
__device__ __forceinline__ void cp_commit_wait(){
    asm volatile("cp.async.commit_group;");
    asm volatile("cp.async.wait_group 0;" ::: "memory");
}
__device__ __forceinline__ uint32_t packbf(float x, float y){
    __nv_bfloat162 h = __floats2bfloat162_rn(x, y);
    uint32_t u; memcpy(&u, &h, 4); return u;
}
__device__ __forceinline__ float2 unpackbf(uint32_t u){
    __nv_bfloat162 h; memcpy(&h, &u, 4);
    return make_float2(__low2float(h), __high2float(h));
}
__device__ __forceinline__ float sigf(float x){
    return 1.f/(1.f + __expf(-x));
}

// ---------------------------------------------------------------------------
// Kernel A: coalesced transpose+convert of the 5 weights -> g_WT [n][k] bf16
// ---------------------------------------------------------------------------
__global__ void __launch_bounds__(256) wconv_kernel(
    const float* __restrict__ Wq, const float* __restrict__ Wk,
    const float* __restrict__ Wv, const float* __restrict__ Wg,
    const float* __restrict__ Wo)
{
    asm volatile("griddepcontrol.launch_dependents;" ::: "memory");
    const float* src[5] = {Wq, Wk, Wv, Wg, Wo};
    const float* W = src[blockIdx.x];
    __nv_bfloat16* dst = g_WT[blockIdx.x];
    __shared__ float tile[32][33];
    int n0 = blockIdx.y * 32;
    int k0 = blockIdx.z * 32;
    int tx = threadIdx.x & 31, ty = threadIdx.x >> 5;

    #pragma unroll
    for (int r = 0; r < 4; r++)
        tile[ty + 8*r][tx] = W[(k0 + ty + 8*r)*128 + n0 + tx];
    __syncthreads();
    #pragma unroll
    for (int p = 0; p < 2; p++){
        int idx = threadIdx.x + p*256;
        int nl = idx >> 4, kl = idx & 15;
        *(uint32_t*)(dst + (n0 + nl)*128 + k0 + 2*kl) =
            packbf(tile[2*kl][nl], tile[2*kl+1][nl]);
    }
}

// ---------------------------------------------------------------------------
// Kernel B: fused LN + bias-proj + pairb copy + q/k/v projections.
// PDL on wconv. smem: zs[128][136] + 2 x wbuf[128][136] = 104448 B, 2 CTA/SM.
// ---------------------------------------------------------------------------
__global__ void __launch_bounds__(256,2) proj_kernel(
    const float* __restrict__ pair, const float* __restrict__ ln_g,
    const float* __restrict__ ln_b, const float* __restrict__ Wbias)
{
    extern __shared__ __nv_bfloat16 sm[];
    __nv_bfloat16* zs = sm;                           // [128][136]
    __nv_bfloat16* bufs[2] = { sm + 17408, sm + 2*17408 };
    int tid  = threadIdx.x;
    int lane = tid & 31;
    int w    = tid >> 5;
    int r0   = blockIdx.x * 128;
    int wm   = w & 3;
    int wn   = (w >> 2) * 64;
    int ec   = 2 * (lane & 3);

    // ---- LayerNorm + Wbias projection + pairb copy (independent of wconv) --
    {
        int row = tid >> 1, half = tid & 1;
        const float4* px = (const float4*)(pair + (size_t)(r0+row)*CZ + half*64);
        float4 xv[16];
        float s1 = 0.f, s2 = 0.f;
        #pragma unroll
        for (int i = 0; i < 16; i++){
            xv[i] = px[i];
            s1 += xv[i].x + xv[i].y + xv[i].z + xv[i].w;
            s2 += xv[i].x*xv[i].x + xv[i].y*xv[i].y + xv[i].z*xv[i].z + xv[i].w*xv[i].w;
        }
        s1 += __shfl_xor_sync(0xffffffffu, s1, 1);
        s2 += __shfl_xor_sync(0xffffffffu, s2, 1);
        float mu  = s1 * (1.f/128.f);
        float inv = rsqrtf(s2 * (1.f/128.f) - mu*mu + 1e-5f);
        float p0=0.f, p1=0.f, p2=0.f, p3=0.f;
        const float4* lg4 = (const float4*)ln_g + half*16;
        const float4* lb4 = (const float4*)ln_b + half*16;
        const float4* wb4 = (const float4*)Wbias;
        #pragma unroll
        for (int i = 0; i < 16; i++){
            float4 g = lg4[i], b = lb4[i];
            int c = half*64 + i*4;
            float z0 = (xv[i].x-mu)*inv*g.x + b.x;
            float z1 = (xv[i].y-mu)*inv*g.y + b.y;
            float z2 = (xv[i].z-mu)*inv*g.z + b.z;
            float z3 = (xv[i].w-mu)*inv*g.w + b.w;
            float4 w0 = wb4[c+0]; p0 = fmaf(z0,w0.x,p0); p1 = fmaf(z0,w0.y,p1); p2 = fmaf(z0,w0.z,p2); p3 = fmaf(z0,w0.w,p3);
            float4 w1 = wb4[c+1]; p0 = fmaf(z1,w1.x,p0); p1 = fmaf(z1,w1.y,p1); p2 = fmaf(z1,w1.z,p2); p3 = fmaf(z1,w1.w,p3);
            float4 w2 = wb4[c+2]; p0 = fmaf(z2,w2.x,p0); p1 = fmaf(z2,w2.y,p1); p2 = fmaf(z2,w2.z,p2); p3 = fmaf(z2,w2.w,p3);
            float4 w3 = wb4[c+3]; p0 = fmaf(z3,w3.x,p0); p1 = fmaf(z3,w3.y,p1); p2 = fmaf(z3,w3.z,p2); p3 = fmaf(z3,w3.w,p3);
            *(uint2*)(zs + row*136 + c) = make_uint2(packbf(z0,z1), packbf(z2,z3));
            *(uint2*)(g_pairb + (size_t)(r0+row)*128 + c) =
                make_uint2(packbf(xv[i].x,xv[i].y), packbf(xv[i].z,xv[i].w));
        }
        p0 += __shfl_xor_sync(0xffffffffu, p0, 1);
        p1 += __shfl_xor_sync(0xffffffffu, p1, 1);
        p2 += __shfl_xor_sync(0xffffffffu, p2, 1);
        p3 += __shfl_xor_sync(0xffffffffu, p3, 1);
        if (half == 0){
            int r = r0 + row;
            g_biasb[0*MT + r] = __float2bfloat16_rn(p0);
            g_biasb[1*MT + r] = __float2bfloat16_rn(p1);
            g_biasb[2*MT + r] = __float2bfloat16_rn(p2);
            g_biasb[3*MT + r] = __float2bfloat16_rn(p3);
        }
    }

    asm volatile("griddepcontrol.wait;" ::: "memory");
    for (int ii = tid; ii < 2048; ii += 256){
        int r = ii >> 4, c = ii & 15;
        cp16(bufs[0] + r*136 + c*8, g_WT[0] + r*128 + c*8);
    }
    cp_commit_wait();
    __syncthreads();

    __nv_bfloat16* Ol[3] = {g_qb, g_kb, g_vb};
    for (int widx = 0; widx < 3; widx++){
        const __nv_bfloat16* cur = bufs[widx & 1];
        if (widx < 2){
            __nv_bfloat16* nxt = bufs[(widx+1) & 1];
            const __nv_bfloat16* wsrc = g_WT[widx+1];
            for (int ii = tid; ii < 2048; ii += 256){
                int r = ii >> 4, c = ii & 15;
                cp16(nxt + r*136 + c*8, wsrc + r*128 + c*8);
            }
            asm volatile("cp.async.commit_group;");
        }
        float scale = (widx == 0) ? 0.1767766952966369f : 1.0f;
        uint32_t* dst = (uint32_t*)Ol[widx];
        #pragma unroll
        for (int jh = 0; jh < 2; jh++){
            int wn2 = wn + jh*32;
            float acc[2][4][4] = {};
            #pragma unroll
            for (int ksp = 0; ksp < 8; ksp++){
                uint32_t af[2][4];
                #pragma unroll
                for (int t = 0; t < 2; t++)
                    ldsm_x4(af[t], zs + (wm*32 + 16*t + (lane&15))*136
                                       + ksp*16 + 8*(lane>>4));
                uint32_t bf[4][2];
                #pragma unroll
                for (int g = 0; g < 2; g++){
                    uint32_t r4[4];
                    ldsm_x4(r4, cur + (wn2 + 16*g + (lane&7) + 8*((lane>>3)&1))*136
                                    + ksp*16 + 8*(lane>>4));
                    bf[2*g][0]=r4[0];   bf[2*g][1]=r4[2];
                    bf[2*g+1][0]=r4[1]; bf[2*g+1][1]=r4[3];
                }
                #pragma unroll
                for (int t = 0; t < 2; t++)
                    #pragma unroll
                    for (int j = 0; j < 4; j++)
                        mma_bf16(acc[t][j], af[t], bf[j][0], bf[j][1]);
            }
            #pragma unroll
            for (int t = 0; t < 2; t++)
                #pragma unroll
                for (int j = 0; j < 4; j++){
                    int row = r0 + wm*32 + 16*t + (lane>>2);
                    int col = wn2 + 8*j + ec;
                    dst[((size_t)row*128 + col) >> 1]     = packbf(acc[t][j][0]*scale, acc[t][j][1]*scale);
                    dst[((size_t)(row+8)*128 + col) >> 1] = packbf(acc[t][j][2]*scale, acc[t][j][3]*scale);
                }
        }
        if (widx < 2)
            asm volatile("cp.async.wait_group 0;" ::: "memory");
        __syncthreads();
    }
}

// ---------------------------------------------------------------------------
// Kernel C: flash attention. Bias chunk staged into smem (bf16, padded rows)
// per nc via cp.async, overlapped with the QK mmas; fragment reads via LDS.
// smem: Qs/Ks/Vs [256][40] + Bs[256][72] = 98304 B, 2 CTA/SM. PDL trigger.
// ---------------------------------------------------------------------------
__global__ void __launch_bounds__(256,2) attn_kernel()
{
    extern __shared__ __nv_bfloat16 smA[];
    __nv_bfloat16* Qs = smA;              // [256][40]
    __nv_bfloat16* Ks = smA + 256*40;     // [256][40]
    __nv_bfloat16* Vs = smA + 2*256*40;   // [256][40]
    __nv_bfloat16* Bs = smA + 3*256*40;   // [256][72] bias chunk (padded)

    int h = blockIdx.x, i = blockIdx.y;
    int tid = threadIdx.x;
    int lane = tid & 31, w = tid >> 5;
    int wrow = w * 32;

    for (int ii = tid; ii < 1024; ii += 256){
        int r = ii >> 2, c = ii & 3;
        size_t go = (size_t)(i*256 + r)*128 + h*32 + c*8;
        cp16(Qs + r*40 + c*8, g_qb + go);
        cp16(Ks + r*40 + c*8, g_kb + go);
        cp16(Vs + r*40 + c*8, g_vb + go);
    }
    asm volatile("griddepcontrol.launch_dependents;" ::: "memory");
    cp_commit_wait();
    __syncthreads();

    uint32_t qa[2][2][4];
    #pragma unroll
    for (int t = 0; t < 2; t++)
        #pragma unroll
        for (int s = 0; s < 2; s++)
            ldsm_x4(qa[t][s], Qs + (wrow + 16*t + (lane&15))*40 + s*16 + 8*(lane>>4));

    float ls[2][2] = {};
    float oacc[2][4][4] = {};
    const __nv_bfloat16* bias_b = g_biasb + (size_t)h*MT;

    for (int nc = 0; nc < 4; nc++){
        // stage bias chunk [256 rows x 64 cols] -> Bs (8 cp16 per thread)
        #pragma unroll
        for (int p = 0; p < 8; p++){
            int ii = tid + p*256;
            int r = ii >> 3, c = ii & 7;
            cp16(Bs + r*72 + c*8, bias_b + (size_t)r*256 + nc*64 + c*8);
        }
        asm volatile("cp.async.commit_group;");

        // QK mmas (bias NOT in init; added in exp phase)
        float sacc[2][8][4] = {};
        #pragma unroll
        for (int s = 0; s < 2; s++){
            uint32_t kb[8][2];
            #pragma unroll
            for (int g = 0; g < 4; g++){
                uint32_t r[4];
                ldsm_x4(r, Ks + (nc*64 + 16*g + (lane&7) + 8*((lane>>3)&1))*40
                              + s*16 + 8*(lane>>4));
                kb[2*g][0]=r[0]; kb[2*g][1]=r[2];
                kb[2*g+1][0]=r[1]; kb[2*g+1][1]=r[3];
            }
            #pragma unroll
            for (int t = 0; t < 2; t++)
                #pragma unroll
                for (int j = 0; j < 8; j++)
                    mma_bf16(sacc[t][j], qa[t][s], kb[j][0], kb[j][1]);
        }

        asm volatile("cp.async.wait_group 0;" ::: "memory");
        __syncthreads();   // bias chunk visible

        uint32_t paf[2][4][4];
        #pragma unroll
        for (int t = 0; t < 2; t++){
            int rl = wrow + 16*t + (lane>>2);
            float rs0 = 0.f, rs1 = 0.f;
            #pragma unroll
            for (int j = 0; j < 8; j++){
                int cc = 8*j + 2*(lane&3);
                float2 b01 = unpackbf(*(const uint32_t*)(Bs + rl*72 + cc));
                float2 b23 = unpackbf(*(const uint32_t*)(Bs + (rl+8)*72 + cc));
                float p0 = __expf(sacc[t][j][0] + b01.x);
                float p1 = __expf(sacc[t][j][1] + b01.y);
                float p2 = __expf(sacc[t][j][2] + b23.x);
                float p3 = __expf(sacc[t][j][3] + b23.y);
                rs0 += p0 + p1; rs1 += p2 + p3;
                int s = j >> 1;
                if (!(j & 1)){ paf[t][s][0]=packbf(p0,p1); paf[t][s][1]=packbf(p2,p3); }
                else         { paf[t][s][2]=packbf(p0,p1); paf[t][s][3]=packbf(p2,p3); }
            }
            ls[t][0] += rs0;
            ls[t][1] += rs1;
        }
        __syncthreads();   // bias reads done; Bs reusable next nc

        #pragma unroll
        for (int s = 0; s < 4; s++){
            uint32_t vb[4][2];
            #pragma unroll
            for (int g = 0; g < 2; g++){
                uint32_t r[4];
                ldsm_x4t(r, Vs + (nc*64 + s*16 + (lane&7) + 8*((lane>>3)&1))*40
                               + 16*g + 8*(lane>>4));
                vb[2*g][0]=r[0];   vb[2*g][1]=r[1];
                vb[2*g+1][0]=r[2]; vb[2*g+1][1]=r[3];
            }
            #pragma unroll
            for (int t = 0; t < 2; t++)
                #pragma unroll
                for (int v = 0; v < 4; v++)
                    mma_bf16(oacc[t][v], paf[t][s], vb[v][0], vb[v][1]);
        }
    }

    uint32_t* dst = (uint32_t*)g_attb;
    #pragma unroll
    for (int t = 0; t < 2; t++){
        float l0 = ls[t][0];
        l0 += __shfl_xor_sync(0xffffffffu, l0, 1);
        l0 += __shfl_xor_sync(0xffffffffu, l0, 2);
        float l1 = ls[t][1];
        l1 += __shfl_xor_sync(0xffffffffu, l1, 1);
        l1 += __shfl_xor_sync(0xffffffffu, l1, 2);
        float inv0 = 1.f/l0, inv1 = 1.f/l1;
        #pragma unroll
        for (int v = 0; v < 4; v++){
            int rowg = i*256 + wrow + 16*t + (lane>>2);
            int col  = h*32 + 8*v + 2*(lane&3);
            dst[((size_t)rowg*128 + col) >> 1]     = packbf(oacc[t][v][0]*inv0, oacc[t][v][1]*inv0);
            dst[((size_t)(rowg+8)*128 + col) >> 1] = packbf(oacc[t][v][2]*inv1, oacc[t][v][3]*inv1);
        }
    }
}

// ---------------------------------------------------------------------------
// Kernel D: out = pair + sigmoid(pair@Wg + bg) * (att@Wo + bo)  (R15-exact)
// PDL: gate phase before griddepcontrol.wait; out phase after.
// ---------------------------------------------------------------------------
__global__ void __launch_bounds__(256,2) final_kernel(
    const float* __restrict__ pair, const float* __restrict__ bo,
    const float* __restrict__ bg,   float* __restrict__ out)
{
    extern __shared__ __nv_bfloat16 sm[];
    __nv_bfloat16* as_ = sm;            // [128][136]
    __nv_bfloat16* wgS = sm + 17408;    // [128][136]
    __nv_bfloat16* woS = sm + 2*17408;  // [128][136]
    int tid = threadIdx.x;
    int lane = tid & 31, w = tid >> 5;
    int wm = w & 3, wn = (w >> 2) * 64;
    int ec = 2 * (lane & 3);
    int r0 = blockIdx.x * 128;

    for (int ii = tid; ii < 2048; ii += 256){
        int r = ii >> 4, c = ii & 15;
        cp16(as_ + r*136 + c*8, g_pairb + (size_t)(r0+r)*128 + c*8);
        cp16(wgS + r*136 + c*8, g_WT[3] + r*128 + c*8);
        cp16(woS + r*136 + c*8, g_WT[4] + r*128 + c*8);
    }
    cp_commit_wait();
    __syncthreads();

    uint32_t gate[2][8][2];
    #pragma unroll
    for (int jh = 0; jh < 2; jh++){
        int wn2 = wn + jh*32;
        float acc[2][4][4] = {};
        #pragma unroll
        for (int ksp = 0; ksp < 8; ksp++){
            uint32_t af[2][4];
            #pragma unroll
            for (int t = 0; t < 2; t++)
                ldsm_x4(af[t], as_ + (wm*32 + 16*t + (lane&15))*136
                                    + ksp*16 + 8*(lane>>4));
            uint32_t bf[4][2];
            #pragma unroll
            for (int g = 0; g < 2; g++){
                uint32_t r4[4];
                ldsm_x4(r4, wgS + (wn2 + 16*g + (lane&7) + 8*((lane>>3)&1))*136
                                + ksp*16 + 8*(lane>>4));
                bf[2*g][0]=r4[0];   bf[2*g][1]=r4[2];
                bf[2*g+1][0]=r4[1]; bf[2*g+1][1]=r4[3];
            }
            #pragma unroll
            for (int t = 0; t < 2; t++)
                #pragma unroll
                for (int j = 0; j < 4; j++)
                    mma_bf16(acc[t][j], af[t], bf[j][0], bf[j][1]);
        }
        #pragma unroll
        for (int t = 0; t < 2; t++)
            #pragma unroll
            for (int j = 0; j < 4; j++){
                int col = wn2 + 8*j + ec;
                float2 bg2 = *(const float2*)(bg + col);
                gate[t][jh*4+j][0] = packbf(sigf(acc[t][j][0]+bg2.x), sigf(acc[t][j][1]+bg2.y));
                gate[t][jh*4+j][1] = packbf(sigf(acc[t][j][2]+bg2.x), sigf(acc[t][j][3]+bg2.y));
            }
    }
    __syncthreads();

    asm volatile("griddepcontrol.wait;" ::: "memory");
    for (int ii = tid; ii < 2048; ii += 256){
        int r = ii >> 4, c = ii & 15;
        cp16(as_ + r*136 + c*8, g_attb + (size_t)(r0+r)*128 + c*8);
    }
    cp_commit_wait();
    __syncthreads();

    #pragma unroll
    for (int jh = 0; jh < 2; jh++){
        int wn2 = wn + jh*32;
        float acc[2][4][4] = {};
        #pragma unroll
        for (int ksp = 0; ksp < 8; ksp++){
            uint32_t af[2][4];
            #pragma unroll
            for (int t = 0; t < 2; t++)
                ldsm_x4(af[t], as_ + (wm*32 + 16*t + (lane&15))*136
                                    + ksp*16 + 8*(lane>>4));
            uint32_t bf[4][2];
            #pragma unroll
            for (int g = 0; g < 2; g++){
                uint32_t r4[4];
                ldsm_x4(r4, woS + (wn2 + 16*g + (lane&7) + 8*((lane>>3)&1))*136
                                + ksp*16 + 8*(lane>>4));
                bf[2*g][0]=r4[0];   bf[2*g][1]=r4[2];
                bf[2*g+1][0]=r4[1]; bf[2*g+1][1]=r4[3];
            }
            #pragma unroll
            for (int t = 0; t < 2; t++)
                #pragma unroll
                for (int j = 0; j < 4; j++)
                    mma_bf16(acc[t][j], af[t], bf[j][0], bf[j][1]);
        }
        #pragma unroll
        for (int t = 0; t < 2; t++)
            #pragma unroll
            for (int j = 0; j < 4; j++){
                int row = r0 + wm*32 + 16*t + (lane>>2);
                int col = wn2 + 8*j + ec;
                float2 bo2 = *(const float2*)(bo + col);
                float2 g01 = unpackbf(gate[t][jh*4+j][0]);
                float2 g23 = unpackbf(gate[t][jh*4+j][1]);
                float2 pr0 = *(const float2*)(pair + (size_t)row*128 + col);
                float2 pr1 = *(const float2*)(pair + (size_t)(row+8)*128 + col);
                float2 o0, o1;
                o0.x = pr0.x + g01.x*(acc[t][j][0] + bo2.x);
                o0.y = pr0.y + g01.y*(acc[t][j][1] + bo2.y);
                o1.x = pr1.x + g23.x*(acc[t][j][2] + bo2.x);
                o1.y = pr1.y + g23.y*(acc[t][j][3] + bo2.y);
                *(float2*)(out + (size_t)row*128 + col) = o0;
                *(float2*)(out + (size_t)(row+8)*128 + col) = o1;
            }
    }
}

// ---------------------------------------------------------------------------
extern "C" void kernel_launch(void* const* d_in, const int* in_sizes, int n_in,
                              void* d_out, int out_size)
{
    const float* pair  = (const float*)d_in[0];
    const float* ln_g  = (const float*)d_in[1];
    const float* ln_b  = (const float*)d_in[2];
    const float* Wq    = (const float*)d_in[3];
    const float* Wk    = (const float*)d_in[4];
    const float* Wv    = (const float*)d_in[5];
    const float* Wbias = (const float*)d_in[6];
    const float* Wo    = (const float*)d_in[7];
    const float* bo    = (const float*)d_in[8];
    const float* Wg    = (const float*)d_in[9];
    const float* bg    = (const float*)d_in[10];
    float* out = (float*)d_out;

    const int smem_proj  = 3*17408*2;              // 104448
    const int smem_attn  = (3*256*40 + 256*72)*2;  // 98304
    const int smem_final = 3*17408*2;              // 104448
    cudaFuncSetAttribute(proj_kernel,  cudaFuncAttributeMaxDynamicSharedMemorySize, smem_proj);
    cudaFuncSetAttribute(attn_kernel,  cudaFuncAttributeMaxDynamicSharedMemorySize, smem_attn);
    cudaFuncSetAttribute(final_kernel, cudaFuncAttributeMaxDynamicSharedMemorySize, smem_final);

    dim3 wg(5, 4, 4);
    wconv_kernel<<<wg, 256>>>(Wq, Wk, Wv, Wg, Wo);

    {
        cudaLaunchConfig_t cfg = {};
        cfg.gridDim = dim3(MT/128);
        cfg.blockDim = dim3(256);
        cfg.dynamicSmemBytes = smem_proj;
        cfg.stream = 0;
        cudaLaunchAttribute attrs[1];
        attrs[0].id = cudaLaunchAttributeProgrammaticStreamSerialization;
        attrs[0].val.programmaticStreamSerializationAllowed = 1;
        cfg.attrs = attrs;
        cfg.numAttrs = 1;
        cudaLaunchKernelEx(&cfg, proj_kernel, pair, ln_g, ln_b, Wbias);
    }

    dim3 ag(NH, LSEQ);
    attn_kernel<<<ag, 256, smem_attn>>>();

    {
        cudaLaunchConfig_t cfg = {};
        cfg.gridDim = dim3(MT/128);
        cfg.blockDim = dim3(256);
        cfg.dynamicSmemBytes = smem_final;
        cfg.stream = 0;
        cudaLaunchAttribute attrs[1];
        attrs[0].id = cudaLaunchAttributeProgrammaticStreamSerialization;
        attrs[0].val.programmaticStreamSerializationAllowed = 1;
        cfg.attrs = attrs;
        cfg.numAttrs = 1;
        cudaLaunchKernelEx(&cfg, final_kernel, pair, bo, bg, out);
    }
}